// round 1
// baseline (speedup 1.0000x reference)
#include <cuda_runtime.h>
#include <math.h>

// ---------------- problem constants ----------------
#define Bn   2
#define Sn   2048
#define Dn   1024
#define Hn   8
#define HDn  128
#define Vn   32000
#define Ln   6
#define Mtok (Bn*Sn)      // 4096
#define FFn  (4*Dn)       // 4096
#define SCALE_ 0.08838834764831845f   // 128^-0.5

// ---------------- scratch (device globals; no cudaMalloc allowed) ----------------
__device__ float g_h  [(size_t)Mtok*Dn];
__device__ float g_ln [(size_t)Mtok*Dn];
__device__ float g_q  [(size_t)Mtok*Dn];
__device__ float g_k  [(size_t)Mtok*Dn];
__device__ float g_v  [(size_t)Mtok*Dn];
__device__ float g_sc [(size_t)Bn*Hn*Sn*Sn];   // 256 MB scores
__device__ float g_ao [(size_t)Mtok*Dn];
__device__ float g_mid[(size_t)Mtok*FFn];

// ---------------- block reductions ----------------
__device__ __forceinline__ float blockReduceSum(float v, float* sm) {
    int lane = threadIdx.x & 31, wid = threadIdx.x >> 5;
    #pragma unroll
    for (int o = 16; o > 0; o >>= 1) v += __shfl_xor_sync(0xffffffffu, v, o);
    if (lane == 0) sm[wid] = v;
    __syncthreads();
    if (threadIdx.x < 32) {
        float t = (threadIdx.x < 8) ? sm[threadIdx.x] : 0.f;
        #pragma unroll
        for (int o = 4; o > 0; o >>= 1) t += __shfl_xor_sync(0xffffffffu, t, o);
        if (threadIdx.x == 0) sm[0] = t;
    }
    __syncthreads();
    float r = sm[0];
    __syncthreads();
    return r;
}

__device__ __forceinline__ float blockReduceMax(float v, float* sm) {
    int lane = threadIdx.x & 31, wid = threadIdx.x >> 5;
    #pragma unroll
    for (int o = 16; o > 0; o >>= 1) v = fmaxf(v, __shfl_xor_sync(0xffffffffu, v, o));
    if (lane == 0) sm[wid] = v;
    __syncthreads();
    if (threadIdx.x < 32) {
        float t = (threadIdx.x < 8) ? sm[threadIdx.x] : -INFINITY;
        #pragma unroll
        for (int o = 4; o > 0; o >>= 1) t = fmaxf(t, __shfl_xor_sync(0xffffffffu, t, o));
        if (threadIdx.x == 0) sm[0] = t;
    }
    __syncthreads();
    float r = sm[0];
    __syncthreads();
    return r;
}

// ---------------- embedding gather ----------------
__global__ void embed_kernel(const int* __restrict__ x,
                             const float* __restrict__ emb,
                             float* __restrict__ h) {
    int t = blockIdx.x;
    int tok = x[t];
    ((float4*)(h + (size_t)t*Dn))[threadIdx.x] =
        ((const float4*)(emb + (size_t)tok*Dn))[threadIdx.x];
}

// ---------------- LayerNorm (optionally two LNs fused) ----------------
__global__ __launch_bounds__(256)
void ln_kernel(const float* __restrict__ x,
               const float* __restrict__ g,  const float* __restrict__ b,
               const float* __restrict__ g2, const float* __restrict__ b2,
               float* __restrict__ y, int dbl) {
    __shared__ float sm[32];
    int row = blockIdx.x;
    float4 v = ((const float4*)(x + (size_t)row*Dn))[threadIdx.x];
    float s  = v.x + v.y + v.z + v.w;
    float ss = v.x*v.x + v.y*v.y + v.z*v.z + v.w*v.w;
    float sum   = blockReduceSum(s, sm);
    float sumsq = blockReduceSum(ss, sm);
    float mean = sum * (1.f/Dn);
    float var  = sumsq * (1.f/Dn) - mean*mean;
    float r = rsqrtf(var + 1e-5f);
    int c = threadIdx.x * 4;
    float4 gv = *(const float4*)(g + c);
    float4 bv = *(const float4*)(b + c);
    float4 o;
    o.x = (v.x - mean)*r*gv.x + bv.x;
    o.y = (v.y - mean)*r*gv.y + bv.y;
    o.z = (v.z - mean)*r*gv.z + bv.z;
    o.w = (v.w - mean)*r*gv.w + bv.w;
    if (dbl) {
        s  = o.x + o.y + o.z + o.w;
        ss = o.x*o.x + o.y*o.y + o.z*o.z + o.w*o.w;
        sum   = blockReduceSum(s, sm);
        sumsq = blockReduceSum(ss, sm);
        mean = sum * (1.f/Dn);
        var  = sumsq * (1.f/Dn) - mean*mean;
        r = rsqrtf(var + 1e-5f);
        float4 g2v = *(const float4*)(g2 + c);
        float4 b2v = *(const float4*)(b2 + c);
        o.x = (o.x - mean)*r*g2v.x + b2v.x;
        o.y = (o.y - mean)*r*g2v.y + b2v.y;
        o.z = (o.z - mean)*r*g2v.z + b2v.z;
        o.w = (o.w - mean)*r*g2v.w + b2v.w;
    }
    ((float4*)(y + (size_t)row*Dn))[threadIdx.x] = o;
}

// ---------------- SGEMM: C = A[MxK] * B[KxN] (+bias)(+add)(relu) ----------------
#define BM 128
#define BN 128
#define BK 16
__global__ __launch_bounds__(256, 2)
void sgemm_kernel(const float* __restrict__ A, const float* __restrict__ B,
                  const float* __restrict__ bias, const float* __restrict__ add,
                  float* __restrict__ C, int M, int N, int K, int relu) {
    __shared__ float As[BK][BM];
    __shared__ float Bs[BK][BN];
    int tid  = threadIdx.x;
    int brow = blockIdx.y * BM;
    int bcol = blockIdx.x * BN;

    int arow0 = tid >> 2;            // 0..63 (and +64)
    int acol0 = (tid & 3) << 2;      // 0..12
    int brl   = tid >> 5;            // 0..7 (and +8)
    int bcl   = (tid & 31) << 2;     // 0..124

    const float* Ap = A + (size_t)brow * K;
    const float* Bp = B + bcol;

    float4 a0 = *(const float4*)(Ap + (size_t)arow0      * K + acol0);
    float4 a1 = *(const float4*)(Ap + (size_t)(arow0+64) * K + acol0);
    float4 b0 = *(const float4*)(Bp + (size_t)brl     * N + bcl);
    float4 b1 = *(const float4*)(Bp + (size_t)(brl+8) * N + bcl);

    int ty = tid >> 4, tx = tid & 15;
    float acc[8][8] = {};

    for (int k0 = 0; k0 < K; k0 += BK) {
        if (k0) __syncthreads();
        As[acol0+0][arow0] = a0.x; As[acol0+1][arow0] = a0.y;
        As[acol0+2][arow0] = a0.z; As[acol0+3][arow0] = a0.w;
        As[acol0+0][arow0+64] = a1.x; As[acol0+1][arow0+64] = a1.y;
        As[acol0+2][arow0+64] = a1.z; As[acol0+3][arow0+64] = a1.w;
        *(float4*)&Bs[brl][bcl]   = b0;
        *(float4*)&Bs[brl+8][bcl] = b1;
        __syncthreads();
        if (k0 + BK < K) {
            const float* An = Ap + (k0 + BK);
            const float* Bnp = Bp + (size_t)(k0 + BK) * N;
            a0 = *(const float4*)(An + (size_t)arow0      * K + acol0);
            a1 = *(const float4*)(An + (size_t)(arow0+64) * K + acol0);
            b0 = *(const float4*)(Bnp + (size_t)brl     * N + bcl);
            b1 = *(const float4*)(Bnp + (size_t)(brl+8) * N + bcl);
        }
        #pragma unroll
        for (int kk = 0; kk < BK; kk++) {
            float4 av0 = *(const float4*)&As[kk][ty*8];
            float4 av1 = *(const float4*)&As[kk][ty*8+4];
            float4 bv0 = *(const float4*)&Bs[kk][tx*8];
            float4 bv1 = *(const float4*)&Bs[kk][tx*8+4];
            float ar[8] = {av0.x,av0.y,av0.z,av0.w, av1.x,av1.y,av1.z,av1.w};
            float br[8] = {bv0.x,bv0.y,bv0.z,bv0.w, bv1.x,bv1.y,bv1.z,bv1.w};
            #pragma unroll
            for (int i = 0; i < 8; i++)
                #pragma unroll
                for (int j = 0; j < 8; j++)
                    acc[i][j] = fmaf(ar[i], br[j], acc[i][j]);
        }
    }

    #pragma unroll
    for (int i = 0; i < 8; i++) {
        int row = brow + ty*8 + i;
        #pragma unroll
        for (int j = 0; j < 8; j += 4) {
            int col = bcol + tx*8 + j;
            float4 o = make_float4(acc[i][j], acc[i][j+1], acc[i][j+2], acc[i][j+3]);
            if (bias) {
                float4 bb = *(const float4*)(bias + col);
                o.x += bb.x; o.y += bb.y; o.z += bb.z; o.w += bb.w;
            }
            if (relu) {
                o.x = fmaxf(o.x, 0.f); o.y = fmaxf(o.y, 0.f);
                o.z = fmaxf(o.z, 0.f); o.w = fmaxf(o.w, 0.f);
            }
            if (add) {
                float4 rr = *(const float4*)(add + (size_t)row*N + col);
                o.x += rr.x; o.y += rr.y; o.z += rr.z; o.w += rr.w;
            }
            *(float4*)(C + (size_t)row*N + col) = o;
        }
    }
}

// ---------------- QK^T with fused rel-pos bias + causal mask ----------------
// scores[bh, i, j] = (q[b,i,h,:]·k[b,j,h,:] + rel[bucket(i,j)][h]*SCALE)*SCALE
__global__ __launch_bounds__(256)
void qk_kernel(const float* __restrict__ q, const float* __restrict__ k,
               const float* __restrict__ rel, float* __restrict__ scores) {
    int ti = blockIdx.y, tj = blockIdx.x;
    if (tj > ti) return;                // causal: lower-triangular tiles only
    int bh = blockIdx.z, b = bh >> 3, h = bh & 7;
    __shared__ float qs[32][68];        // [d][row], padded for store conflicts + 16B align
    __shared__ float ks[32][68];
    int tid  = threadIdx.x;
    int lrow = tid >> 3;                // 0..31
    int lcol = (tid & 7) << 2;          // 0..28
    const float* qb = q + ((size_t)b*Sn + ti*64)*Dn + h*HDn;
    const float* kb = k + ((size_t)b*Sn + tj*64)*Dn + h*HDn;
    int ty = tid >> 4, tx = tid & 15;
    float acc[4][4] = {};
    for (int d0 = 0; d0 < HDn; d0 += 32) {
        float4 q0 = *(const float4*)(qb + (size_t)lrow*Dn      + d0 + lcol);
        float4 q1 = *(const float4*)(qb + (size_t)(lrow+32)*Dn + d0 + lcol);
        float4 k0 = *(const float4*)(kb + (size_t)lrow*Dn      + d0 + lcol);
        float4 k1 = *(const float4*)(kb + (size_t)(lrow+32)*Dn + d0 + lcol);
        __syncthreads();
        qs[lcol+0][lrow] = q0.x; qs[lcol+1][lrow] = q0.y;
        qs[lcol+2][lrow] = q0.z; qs[lcol+3][lrow] = q0.w;
        qs[lcol+0][lrow+32] = q1.x; qs[lcol+1][lrow+32] = q1.y;
        qs[lcol+2][lrow+32] = q1.z; qs[lcol+3][lrow+32] = q1.w;
        ks[lcol+0][lrow] = k0.x; ks[lcol+1][lrow] = k0.y;
        ks[lcol+2][lrow] = k0.z; ks[lcol+3][lrow] = k0.w;
        ks[lcol+0][lrow+32] = k1.x; ks[lcol+1][lrow+32] = k1.y;
        ks[lcol+2][lrow+32] = k1.z; ks[lcol+3][lrow+32] = k1.w;
        __syncthreads();
        #pragma unroll
        for (int d = 0; d < 32; d++) {
            float4 a = *(const float4*)&qs[d][ty<<2];
            float4 c = *(const float4*)&ks[d][tx<<2];
            float ar[4] = {a.x,a.y,a.z,a.w};
            float cr[4] = {c.x,c.y,c.z,c.w};
            #pragma unroll
            for (int ii = 0; ii < 4; ii++)
                #pragma unroll
                for (int jj = 0; jj < 4; jj++)
                    acc[ii][jj] = fmaf(ar[ii], cr[jj], acc[ii][jj]);
        }
    }
    float* sb = scores + (size_t)bh*Sn*Sn;
    float inv_log8 = 1.0f / logf(8.0f);
    #pragma unroll
    for (int ii = 0; ii < 4; ii++) {
        int i = ti*64 + (ty<<2) + ii;
        #pragma unroll
        for (int jj = 0; jj < 4; jj++) {
            int j = tj*64 + (tx<<2) + jj;
            float val;
            if (j > i) {
                val = -INFINITY;
            } else {
                int n = i - j;
                int bucket;
                if (n < 16) bucket = n;
                else {
                    int vb = 16 + (int)((logf((float)n * (1.0f/16.0f)) * inv_log8) * 16.0f);
                    bucket = vb < 31 ? vb : 31;
                }
                val = (acc[ii][jj] + rel[bucket*Hn + h]*SCALE_) * SCALE_;
            }
            sb[(size_t)i*Sn + j] = val;
        }
    }
}

// ---------------- causal row softmax (+zero-pad diagonal tile) ----------------
__global__ __launch_bounds__(256)
void softmax_kernel(float* __restrict__ scores) {
    __shared__ float sm[32];
    int i = blockIdx.x, bh = blockIdx.y;
    float* row = scores + ((size_t)bh*Sn + i)*Sn;
    int len = i + 1;
    float m = -INFINITY;
    for (int j = threadIdx.x; j < len; j += 256) m = fmaxf(m, row[j]);
    m = blockReduceMax(m, sm);
    float s = 0.f;
    for (int j = threadIdx.x; j < len; j += 256) {
        float e = __expf(row[j] - m);
        row[j] = e;
        s += e;
    }
    float sum = blockReduceSum(s, sm);
    float inv = 1.f / sum;
    for (int j = threadIdx.x; j < len; j += 256) row[j] *= inv;
    int pad = ((i >> 6) + 1) << 6;
    if (pad > Sn) pad = Sn;
    for (int j = len + threadIdx.x; j < pad; j += 256) row[j] = 0.f;
}

// ---------------- AV: out[b,i,h,:] = sum_j P[i,j] * v[b,j,h,:] ----------------
__global__ __launch_bounds__(256)
void av_kernel(const float* __restrict__ scores, const float* __restrict__ v,
               float* __restrict__ out) {
    int ti = blockIdx.x;
    int bh = blockIdx.y, b = bh >> 3, h = bh & 7;
    __shared__ float ps[64][64];    // [j][i], XOR-swizzled i
    __shared__ float vs[64][128];   // [j][col]
    int tid = threadIdx.x;
    int ty = tid >> 4, tx = tid & 15;
    const float* sb = scores + ((size_t)bh*Sn + ti*64)*Sn;
    const float* vb = v + ((size_t)b*Sn)*Dn + h*HDn;
    float acc[4][8] = {};
    int prow = tid >> 4;            // 0..15
    int pcol = (tid & 15) << 2;     // 0..60
    int vrow = tid >> 5;            // 0..7
    int vcol = (tid & 31) << 2;     // 0..124
    for (int jt = 0; jt <= ti; jt++) {
        if (jt) __syncthreads();
        #pragma unroll
        for (int r = 0; r < 4; r++) {
            int il = prow + 16*r;   // local i
            float4 p = *(const float4*)(sb + (size_t)il*Sn + jt*64 + pcol);
            float pv[4] = {p.x, p.y, p.z, p.w};
            #pragma unroll
            for (int c = 0; c < 4; c++) {
                int d = pcol + c;   // local j
                int ip = ((((il >> 2) ^ (d & 15)) << 2) | (il & 3));
                ps[d][ip] = pv[c];
            }
        }
        #pragma unroll
        for (int r = 0; r < 8; r++) {
            float4 vv = *(const float4*)(vb + (size_t)(jt*64 + vrow + 8*r)*Dn + vcol);
            *(float4*)&vs[vrow + 8*r][vcol] = vv;
        }
        __syncthreads();
        #pragma unroll
        for (int d = 0; d < 64; d++) {
            float4 a  = *(const float4*)&ps[d][((ty ^ (d & 15)) << 2)];
            float4 b0 = *(const float4*)&vs[d][tx<<3];
            float4 b1 = *(const float4*)&vs[d][(tx<<3)+4];
            float ar[4] = {a.x,a.y,a.z,a.w};
            float br[8] = {b0.x,b0.y,b0.z,b0.w, b1.x,b1.y,b1.z,b1.w};
            #pragma unroll
            for (int ii = 0; ii < 4; ii++)
                #pragma unroll
                for (int jj = 0; jj < 8; jj++)
                    acc[ii][jj] = fmaf(ar[ii], br[jj], acc[ii][jj]);
        }
    }
    #pragma unroll
    for (int ii = 0; ii < 4; ii++) {
        int i = ti*64 + (ty<<2) + ii;
        float* op = out + ((size_t)b*Sn + i)*Dn + h*HDn + (tx<<3);
        *(float4*)op       = make_float4(acc[ii][0], acc[ii][1], acc[ii][2], acc[ii][3]);
        *(float4*)(op + 4) = make_float4(acc[ii][4], acc[ii][5], acc[ii][6], acc[ii][7]);
    }
}

// ---------------- orchestration ----------------
extern "C" void kernel_launch(void* const* d_in, const int* in_sizes, int n_in,
                              void* d_out, int out_size) {
    (void)in_sizes; (void)n_in; (void)out_size;
    const int*   x     = (const int*)  d_in[0];
    const float* tok   = (const float*)d_in[1];
    const float* rel   = (const float*)d_in[2];
    const float* ln_g  = (const float*)d_in[3];
    const float* ln_b  = (const float*)d_in[4];
    const float* Wqkv  = (const float*)d_in[5];
    const float* bqkv  = (const float*)d_in[6];
    const float* Wo    = (const float*)d_in[7];
    const float* bo    = (const float*)d_in[8];
    const float* W1    = (const float*)d_in[9];
    const float* b1    = (const float*)d_in[10];
    const float* W2    = (const float*)d_in[11];
    const float* b2    = (const float*)d_in[12];
    const float* lnf_g = (const float*)d_in[13];
    const float* lnf_b = (const float*)d_in[14];
    const float* Whead = (const float*)d_in[15];
    const float* bhead = (const float*)d_in[16];
    float* out = (float*)d_out;

    float *h, *ln, *q, *k, *v, *sc, *ao, *mid;
    cudaGetSymbolAddress((void**)&h,   g_h);
    cudaGetSymbolAddress((void**)&ln,  g_ln);
    cudaGetSymbolAddress((void**)&q,   g_q);
    cudaGetSymbolAddress((void**)&k,   g_k);
    cudaGetSymbolAddress((void**)&v,   g_v);
    cudaGetSymbolAddress((void**)&sc,  g_sc);
    cudaGetSymbolAddress((void**)&ao,  g_ao);
    cudaGetSymbolAddress((void**)&mid, g_mid);

    embed_kernel<<<Mtok, 256>>>(x, tok, h);

    dim3 gDD(Dn/BN,  Mtok/BM);   // 8 x 32
    dim3 gDF(FFn/BN, Mtok/BM);   // 32 x 32
    dim3 gDV(Vn/BN,  Mtok/BM);   // 250 x 32

    for (int l = 0; l < Ln; l++) {
        // attn LN
        ln_kernel<<<Mtok, 256>>>(h, ln_g + (size_t)(l*3+0)*Dn, ln_b + (size_t)(l*3+0)*Dn,
                                 nullptr, nullptr, ln, 0);
        // QKV projections
        sgemm_kernel<<<gDD, 256>>>(ln, Wqkv + (size_t)(l*3+0)*Dn*Dn,
                                   bqkv + (size_t)(l*3+0)*Dn, nullptr, q, Mtok, Dn, Dn, 0);
        sgemm_kernel<<<gDD, 256>>>(ln, Wqkv + (size_t)(l*3+1)*Dn*Dn,
                                   bqkv + (size_t)(l*3+1)*Dn, nullptr, k, Mtok, Dn, Dn, 0);
        sgemm_kernel<<<gDD, 256>>>(ln, Wqkv + (size_t)(l*3+2)*Dn*Dn,
                                   bqkv + (size_t)(l*3+2)*Dn, nullptr, v, Mtok, Dn, Dn, 0);
        // attention
        qk_kernel<<<dim3(Sn/64, Sn/64, Bn*Hn), 256>>>(q, k, rel, sc);
        softmax_kernel<<<dim3(Sn, Bn*Hn), 256>>>(sc);
        av_kernel<<<dim3(Sn/64, Bn*Hn), 256>>>(sc, v, ao);
        // output proj + residual
        sgemm_kernel<<<gDD, 256>>>(ao, Wo + (size_t)l*Dn*Dn, bo + (size_t)l*Dn,
                                   h, h, Mtok, Dn, Dn, 0);
        // ln2 then ffn-LN (fused)
        ln_kernel<<<Mtok, 256>>>(h, ln_g + (size_t)(l*3+1)*Dn, ln_b + (size_t)(l*3+1)*Dn,
                                 ln_g + (size_t)(l*3+2)*Dn, ln_b + (size_t)(l*3+2)*Dn, ln, 1);
        // FFN
        sgemm_kernel<<<gDF, 256>>>(ln, W1 + (size_t)l*Dn*FFn, b1 + (size_t)l*FFn,
                                   nullptr, mid, Mtok, FFn, Dn, 1);
        sgemm_kernel<<<gDD, 256>>>(mid, W2 + (size_t)l*FFn*Dn, b2 + (size_t)l*Dn,
                                   h, h, Mtok, Dn, FFn, 0);
    }

    ln_kernel<<<Mtok, 256>>>(h, lnf_g, lnf_b, nullptr, nullptr, ln, 0);
    sgemm_kernel<<<gDV, 256>>>(ln, Whead, bhead, nullptr, out, Mtok, Vn, Dn, 0);
}

// round 2
// speedup vs baseline: 1.9768x; 1.9768x over previous
#include <cuda_runtime.h>
#include <math.h>
#include <stdint.h>

// ---------------- problem constants ----------------
#define Bn   2
#define Sn   2048
#define Dn   1024
#define Hn   8
#define HDn  128
#define Vn   32000
#define Ln   6
#define Mtok (Bn*Sn)      // 4096
#define FFn  (4*Dn)       // 4096
#define SCALE_ 0.08838834764831845f   // 128^-0.5

// ---------------- scratch (device globals; no cudaMalloc allowed) ----------------
__device__ float g_h  [(size_t)Mtok*Dn];
__device__ float g_ln [(size_t)Mtok*Dn];
__device__ float g_q  [(size_t)Mtok*Dn];
__device__ float g_k  [(size_t)Mtok*Dn];
__device__ float g_v  [(size_t)Mtok*Dn];
__device__ float g_sc [(size_t)Bn*Hn*Sn*Sn];   // 256 MB scores
__device__ float g_ao [(size_t)Mtok*Dn];
__device__ float g_mid[(size_t)Mtok*FFn];

// ---------------- helpers ----------------
__device__ __forceinline__ uint32_t f2tf32(float f) {
    uint32_t u;
    asm("cvt.rna.tf32.f32 %0, %1;" : "=r"(u) : "f"(f));
    return u;
}

__device__ __forceinline__ float blockReduceSum(float v, float* sm) {
    int lane = threadIdx.x & 31, wid = threadIdx.x >> 5;
    #pragma unroll
    for (int o = 16; o > 0; o >>= 1) v += __shfl_xor_sync(0xffffffffu, v, o);
    if (lane == 0) sm[wid] = v;
    __syncthreads();
    if (threadIdx.x < 32) {
        float t = (threadIdx.x < 8) ? sm[threadIdx.x] : 0.f;
        #pragma unroll
        for (int o = 4; o > 0; o >>= 1) t += __shfl_xor_sync(0xffffffffu, t, o);
        if (threadIdx.x == 0) sm[0] = t;
    }
    __syncthreads();
    float r = sm[0];
    __syncthreads();
    return r;
}

__device__ __forceinline__ float blockReduceMax(float v, float* sm) {
    int lane = threadIdx.x & 31, wid = threadIdx.x >> 5;
    #pragma unroll
    for (int o = 16; o > 0; o >>= 1) v = fmaxf(v, __shfl_xor_sync(0xffffffffu, v, o));
    if (lane == 0) sm[wid] = v;
    __syncthreads();
    if (threadIdx.x < 32) {
        float t = (threadIdx.x < 8) ? sm[threadIdx.x] : -INFINITY;
        #pragma unroll
        for (int o = 4; o > 0; o >>= 1) t = fmaxf(t, __shfl_xor_sync(0xffffffffu, t, o));
        if (threadIdx.x == 0) sm[0] = t;
    }
    __syncthreads();
    float r = sm[0];
    __syncthreads();
    return r;
}

// ---------------- embedding gather ----------------
__global__ void embed_kernel(const int* __restrict__ x,
                             const float* __restrict__ emb,
                             float* __restrict__ h) {
    int t = blockIdx.x;
    int tok = x[t];
    ((float4*)(h + (size_t)t*Dn))[threadIdx.x] =
        ((const float4*)(emb + (size_t)tok*Dn))[threadIdx.x];
}

// ---------------- LayerNorm (optionally two LNs fused) ----------------
__global__ __launch_bounds__(256)
void ln_kernel(const float* __restrict__ x,
               const float* __restrict__ g,  const float* __restrict__ b,
               const float* __restrict__ g2, const float* __restrict__ b2,
               float* __restrict__ y, int dbl) {
    __shared__ float sm[32];
    int row = blockIdx.x;
    float4 v = ((const float4*)(x + (size_t)row*Dn))[threadIdx.x];
    float s  = v.x + v.y + v.z + v.w;
    float ss = v.x*v.x + v.y*v.y + v.z*v.z + v.w*v.w;
    float sum   = blockReduceSum(s, sm);
    float sumsq = blockReduceSum(ss, sm);
    float mean = sum * (1.f/Dn);
    float var  = sumsq * (1.f/Dn) - mean*mean;
    float r = rsqrtf(var + 1e-5f);
    int c = threadIdx.x * 4;
    float4 gv = *(const float4*)(g + c);
    float4 bv = *(const float4*)(b + c);
    float4 o;
    o.x = (v.x - mean)*r*gv.x + bv.x;
    o.y = (v.y - mean)*r*gv.y + bv.y;
    o.z = (v.z - mean)*r*gv.z + bv.z;
    o.w = (v.w - mean)*r*gv.w + bv.w;
    if (dbl) {
        s  = o.x + o.y + o.z + o.w;
        ss = o.x*o.x + o.y*o.y + o.z*o.z + o.w*o.w;
        sum   = blockReduceSum(s, sm);
        sumsq = blockReduceSum(ss, sm);
        mean = sum * (1.f/Dn);
        var  = sumsq * (1.f/Dn) - mean*mean;
        r = rsqrtf(var + 1e-5f);
        float4 g2v = *(const float4*)(g2 + c);
        float4 b2v = *(const float4*)(b2 + c);
        o.x = (o.x - mean)*r*g2v.x + b2v.x;
        o.y = (o.y - mean)*r*g2v.y + b2v.y;
        o.z = (o.z - mean)*r*g2v.z + b2v.z;
        o.w = (o.w - mean)*r*g2v.w + b2v.w;
    }
    ((float4*)(y + (size_t)row*Dn))[threadIdx.x] = o;
}

// ---------------- TF32 tensor-core GEMM: C = A[MxK] * B[KxN] (+bias)(relu)(+add) ----------------
// CTA tile 128x128x16, 8 warps each 64x32, mma.sync.m16n8k8.tf32
#define TBM 128
#define TBN 128
#define TBK 16
#define APAD 136   // k-major stride: banks = (8k + row) % 32 -> conflict-free frags

__global__ __launch_bounds__(256, 2)
void tgemm_kernel(const float* __restrict__ A, const float* __restrict__ B,
                  const float* __restrict__ bias, const float* __restrict__ add,
                  float* __restrict__ C, int M, int N, int K, int relu) {
    __shared__ float As[TBK][APAD];   // [k][m]
    __shared__ float Bs[TBK][APAD];   // [k][n]

    int tid  = threadIdx.x;
    int brow = blockIdx.y * TBM;
    int bcol = blockIdx.x * TBN;

    int warp = tid >> 5, lane = tid & 31;
    int gid = lane >> 2, tig = lane & 3;
    int warpM = (warp >> 2) * 64;     // 0 or 64
    int warpN = (warp & 3) * 32;      // 0..96

    // global-load mapping
    int arow0 = tid >> 2;             // 0..63
    int acol0 = (tid & 3) << 2;       // 0,4,8,12  (k)
    int brl   = tid >> 5;             // 0..7      (k)
    int bcl   = (tid & 31) << 2;      // 0..124    (n)

    const float* Ap = A + (size_t)brow * K;
    const float* Bp = B + bcol;

    float4 a0 = *(const float4*)(Ap + (size_t)arow0      * K + acol0);
    float4 a1 = *(const float4*)(Ap + (size_t)(arow0+64) * K + acol0);
    float4 b0 = *(const float4*)(Bp + (size_t)brl     * N + bcl);
    float4 b1 = *(const float4*)(Bp + (size_t)(brl+8) * N + bcl);

    float acc[4][4][4] = {};

    for (int k0 = 0; k0 < K; k0 += TBK) {
        if (k0) __syncthreads();
        // stage A (k-major), converted to tf32 bits
        As[acol0+0][arow0]    = __uint_as_float(f2tf32(a0.x));
        As[acol0+1][arow0]    = __uint_as_float(f2tf32(a0.y));
        As[acol0+2][arow0]    = __uint_as_float(f2tf32(a0.z));
        As[acol0+3][arow0]    = __uint_as_float(f2tf32(a0.w));
        As[acol0+0][arow0+64] = __uint_as_float(f2tf32(a1.x));
        As[acol0+1][arow0+64] = __uint_as_float(f2tf32(a1.y));
        As[acol0+2][arow0+64] = __uint_as_float(f2tf32(a1.z));
        As[acol0+3][arow0+64] = __uint_as_float(f2tf32(a1.w));
        // stage B
        float4 tb0, tb1;
        tb0.x = __uint_as_float(f2tf32(b0.x)); tb0.y = __uint_as_float(f2tf32(b0.y));
        tb0.z = __uint_as_float(f2tf32(b0.z)); tb0.w = __uint_as_float(f2tf32(b0.w));
        tb1.x = __uint_as_float(f2tf32(b1.x)); tb1.y = __uint_as_float(f2tf32(b1.y));
        tb1.z = __uint_as_float(f2tf32(b1.z)); tb1.w = __uint_as_float(f2tf32(b1.w));
        *(float4*)&Bs[brl][bcl]   = tb0;
        *(float4*)&Bs[brl+8][bcl] = tb1;
        __syncthreads();
        // prefetch next k-slab
        if (k0 + TBK < K) {
            const float* An  = Ap + (k0 + TBK);
            const float* Bnp = Bp + (size_t)(k0 + TBK) * N;
            a0 = *(const float4*)(An + (size_t)arow0      * K + acol0);
            a1 = *(const float4*)(An + (size_t)(arow0+64) * K + acol0);
            b0 = *(const float4*)(Bnp + (size_t)brl     * N + bcl);
            b1 = *(const float4*)(Bnp + (size_t)(brl+8) * N + bcl);
        }
        #pragma unroll
        for (int ks = 0; ks < 2; ks++) {
            int kb = ks * 8;
            uint32_t af[4][4], bf[4][2];
            #pragma unroll
            for (int mt = 0; mt < 4; mt++) {
                int r = warpM + mt*16 + gid;
                af[mt][0] = __float_as_uint(As[kb+tig  ][r]);
                af[mt][1] = __float_as_uint(As[kb+tig  ][r+8]);
                af[mt][2] = __float_as_uint(As[kb+tig+4][r]);
                af[mt][3] = __float_as_uint(As[kb+tig+4][r+8]);
            }
            #pragma unroll
            for (int nt = 0; nt < 4; nt++) {
                int c = warpN + nt*8 + gid;
                bf[nt][0] = __float_as_uint(Bs[kb+tig  ][c]);
                bf[nt][1] = __float_as_uint(Bs[kb+tig+4][c]);
            }
            #pragma unroll
            for (int mt = 0; mt < 4; mt++)
                #pragma unroll
                for (int nt = 0; nt < 4; nt++) {
                    asm volatile(
                        "mma.sync.aligned.m16n8k8.row.col.f32.tf32.tf32.f32 "
                        "{%0,%1,%2,%3}, {%4,%5,%6,%7}, {%8,%9}, {%0,%1,%2,%3};\n"
                        : "+f"(acc[mt][nt][0]), "+f"(acc[mt][nt][1]),
                          "+f"(acc[mt][nt][2]), "+f"(acc[mt][nt][3])
                        : "r"(af[mt][0]), "r"(af[mt][1]), "r"(af[mt][2]), "r"(af[mt][3]),
                          "r"(bf[nt][0]), "r"(bf[nt][1]));
                }
        }
    }

    // epilogue
    #pragma unroll
    for (int mt = 0; mt < 4; mt++) {
        int r0 = brow + warpM + mt*16 + gid;
        int r1 = r0 + 8;
        #pragma unroll
        for (int nt = 0; nt < 4; nt++) {
            int c = bcol + warpN + nt*8 + tig*2;
            float v00 = acc[mt][nt][0], v01 = acc[mt][nt][1];
            float v10 = acc[mt][nt][2], v11 = acc[mt][nt][3];
            if (bias) {
                float bb0 = bias[c], bb1 = bias[c+1];
                v00 += bb0; v01 += bb1; v10 += bb0; v11 += bb1;
            }
            if (relu) {
                v00 = fmaxf(v00, 0.f); v01 = fmaxf(v01, 0.f);
                v10 = fmaxf(v10, 0.f); v11 = fmaxf(v11, 0.f);
            }
            if (add) {
                const float* ad0 = add + (size_t)r0*N + c;
                const float* ad1 = add + (size_t)r1*N + c;
                v00 += ad0[0]; v01 += ad0[1];
                v10 += ad1[0]; v11 += ad1[1];
            }
            *(float2*)(C + (size_t)r0*N + c) = make_float2(v00, v01);
            *(float2*)(C + (size_t)r1*N + c) = make_float2(v10, v11);
        }
    }
}

// ---------------- QK^T with fused rel-pos bias + causal mask ----------------
__global__ __launch_bounds__(256)
void qk_kernel(const float* __restrict__ q, const float* __restrict__ k,
               const float* __restrict__ rel, float* __restrict__ scores) {
    int ti = blockIdx.y, tj = blockIdx.x;
    if (tj > ti) return;                // causal: lower-triangular tiles only
    int bh = blockIdx.z, b = bh >> 3, h = bh & 7;
    __shared__ float qs[32][68];
    __shared__ float ks[32][68];
    int tid  = threadIdx.x;
    int lrow = tid >> 3;
    int lcol = (tid & 7) << 2;
    const float* qb = q + ((size_t)b*Sn + ti*64)*Dn + h*HDn;
    const float* kb = k + ((size_t)b*Sn + tj*64)*Dn + h*HDn;
    int ty = tid >> 4, tx = tid & 15;
    float acc[4][4] = {};
    for (int d0 = 0; d0 < HDn; d0 += 32) {
        float4 q0 = *(const float4*)(qb + (size_t)lrow*Dn      + d0 + lcol);
        float4 q1 = *(const float4*)(qb + (size_t)(lrow+32)*Dn + d0 + lcol);
        float4 k0 = *(const float4*)(kb + (size_t)lrow*Dn      + d0 + lcol);
        float4 k1 = *(const float4*)(kb + (size_t)(lrow+32)*Dn + d0 + lcol);
        __syncthreads();
        qs[lcol+0][lrow] = q0.x; qs[lcol+1][lrow] = q0.y;
        qs[lcol+2][lrow] = q0.z; qs[lcol+3][lrow] = q0.w;
        qs[lcol+0][lrow+32] = q1.x; qs[lcol+1][lrow+32] = q1.y;
        qs[lcol+2][lrow+32] = q1.z; qs[lcol+3][lrow+32] = q1.w;
        ks[lcol+0][lrow] = k0.x; ks[lcol+1][lrow] = k0.y;
        ks[lcol+2][lrow] = k0.z; ks[lcol+3][lrow] = k0.w;
        ks[lcol+0][lrow+32] = k1.x; ks[lcol+1][lrow+32] = k1.y;
        ks[lcol+2][lrow+32] = k1.z; ks[lcol+3][lrow+32] = k1.w;
        __syncthreads();
        #pragma unroll
        for (int d = 0; d < 32; d++) {
            float4 a = *(const float4*)&qs[d][ty<<2];
            float4 c = *(const float4*)&ks[d][tx<<2];
            float ar[4] = {a.x,a.y,a.z,a.w};
            float cr[4] = {c.x,c.y,c.z,c.w};
            #pragma unroll
            for (int ii = 0; ii < 4; ii++)
                #pragma unroll
                for (int jj = 0; jj < 4; jj++)
                    acc[ii][jj] = fmaf(ar[ii], cr[jj], acc[ii][jj]);
        }
    }
    float* sb = scores + (size_t)bh*Sn*Sn;
    float inv_log8 = 1.0f / logf(8.0f);
    #pragma unroll
    for (int ii = 0; ii < 4; ii++) {
        int i = ti*64 + (ty<<2) + ii;
        #pragma unroll
        for (int jj = 0; jj < 4; jj++) {
            int j = tj*64 + (tx<<2) + jj;
            float val;
            if (j > i) {
                val = -INFINITY;
            } else {
                int n = i - j;
                int bucket;
                if (n < 16) bucket = n;
                else {
                    int vb = 16 + (int)((logf((float)n * (1.0f/16.0f)) * inv_log8) * 16.0f);
                    bucket = vb < 31 ? vb : 31;
                }
                val = (acc[ii][jj] + rel[bucket*Hn + h]*SCALE_) * SCALE_;
            }
            sb[(size_t)i*Sn + j] = val;
        }
    }
}

// ---------------- causal row softmax (+zero-pad diagonal tile) ----------------
__global__ __launch_bounds__(256)
void softmax_kernel(float* __restrict__ scores) {
    __shared__ float sm[32];
    int i = blockIdx.x, bh = blockIdx.y;
    float* row = scores + ((size_t)bh*Sn + i)*Sn;
    int len = i + 1;
    float m = -INFINITY;
    for (int j = threadIdx.x; j < len; j += 256) m = fmaxf(m, row[j]);
    m = blockReduceMax(m, sm);
    float s = 0.f;
    for (int j = threadIdx.x; j < len; j += 256) {
        float e = __expf(row[j] - m);
        row[j] = e;
        s += e;
    }
    float sum = blockReduceSum(s, sm);
    float inv = 1.f / sum;
    for (int j = threadIdx.x; j < len; j += 256) row[j] *= inv;
    int pad = ((i >> 6) + 1) << 6;
    if (pad > Sn) pad = Sn;
    for (int j = len + threadIdx.x; j < pad; j += 256) row[j] = 0.f;
}

// ---------------- AV: out[b,i,h,:] = sum_j P[i,j] * v[b,j,h,:] ----------------
__global__ __launch_bounds__(256)
void av_kernel(const float* __restrict__ scores, const float* __restrict__ v,
               float* __restrict__ out) {
    int ti = blockIdx.x;
    int bh = blockIdx.y, b = bh >> 3, h = bh & 7;
    __shared__ float ps[64][64];
    __shared__ float vs[64][128];
    int tid = threadIdx.x;
    int ty = tid >> 4, tx = tid & 15;
    const float* sb = scores + ((size_t)bh*Sn + ti*64)*Sn;
    const float* vb = v + ((size_t)b*Sn)*Dn + h*HDn;
    float acc[4][8] = {};
    int prow = tid >> 4;
    int pcol = (tid & 15) << 2;
    int vrow = tid >> 5;
    int vcol = (tid & 31) << 2;
    for (int jt = 0; jt <= ti; jt++) {
        if (jt) __syncthreads();
        #pragma unroll
        for (int r = 0; r < 4; r++) {
            int il = prow + 16*r;
            float4 p = *(const float4*)(sb + (size_t)il*Sn + jt*64 + pcol);
            float pv[4] = {p.x, p.y, p.z, p.w};
            #pragma unroll
            for (int c = 0; c < 4; c++) {
                int d = pcol + c;
                int ip = ((((il >> 2) ^ (d & 15)) << 2) | (il & 3));
                ps[d][ip] = pv[c];
            }
        }
        #pragma unroll
        for (int r = 0; r < 8; r++) {
            float4 vv = *(const float4*)(vb + (size_t)(jt*64 + vrow + 8*r)*Dn + vcol);
            *(float4*)&vs[vrow + 8*r][vcol] = vv;
        }
        __syncthreads();
        #pragma unroll
        for (int d = 0; d < 64; d++) {
            float4 a  = *(const float4*)&ps[d][((ty ^ (d & 15)) << 2)];
            float4 b0 = *(const float4*)&vs[d][tx<<3];
            float4 b1 = *(const float4*)&vs[d][(tx<<3)+4];
            float ar[4] = {a.x,a.y,a.z,a.w};
            float br[8] = {b0.x,b0.y,b0.z,b0.w, b1.x,b1.y,b1.z,b1.w};
            #pragma unroll
            for (int ii = 0; ii < 4; ii++)
                #pragma unroll
                for (int jj = 0; jj < 8; jj++)
                    acc[ii][jj] = fmaf(ar[ii], br[jj], acc[ii][jj]);
        }
    }
    #pragma unroll
    for (int ii = 0; ii < 4; ii++) {
        int i = ti*64 + (ty<<2) + ii;
        float* op = out + ((size_t)b*Sn + i)*Dn + h*HDn + (tx<<3);
        *(float4*)op       = make_float4(acc[ii][0], acc[ii][1], acc[ii][2], acc[ii][3]);
        *(float4*)(op + 4) = make_float4(acc[ii][4], acc[ii][5], acc[ii][6], acc[ii][7]);
    }
}

// ---------------- orchestration ----------------
extern "C" void kernel_launch(void* const* d_in, const int* in_sizes, int n_in,
                              void* d_out, int out_size) {
    (void)in_sizes; (void)n_in; (void)out_size;
    const int*   x     = (const int*)  d_in[0];
    const float* tok   = (const float*)d_in[1];
    const float* rel   = (const float*)d_in[2];
    const float* ln_g  = (const float*)d_in[3];
    const float* ln_b  = (const float*)d_in[4];
    const float* Wqkv  = (const float*)d_in[5];
    const float* bqkv  = (const float*)d_in[6];
    const float* Wo    = (const float*)d_in[7];
    const float* bo    = (const float*)d_in[8];
    const float* W1    = (const float*)d_in[9];
    const float* b1    = (const float*)d_in[10];
    const float* W2    = (const float*)d_in[11];
    const float* b2    = (const float*)d_in[12];
    const float* lnf_g = (const float*)d_in[13];
    const float* lnf_b = (const float*)d_in[14];
    const float* Whead = (const float*)d_in[15];
    const float* bhead = (const float*)d_in[16];
    float* out = (float*)d_out;

    float *h, *ln, *q, *k, *v, *sc, *ao, *mid;
    cudaGetSymbolAddress((void**)&h,   g_h);
    cudaGetSymbolAddress((void**)&ln,  g_ln);
    cudaGetSymbolAddress((void**)&q,   g_q);
    cudaGetSymbolAddress((void**)&k,   g_k);
    cudaGetSymbolAddress((void**)&v,   g_v);
    cudaGetSymbolAddress((void**)&sc,  g_sc);
    cudaGetSymbolAddress((void**)&ao,  g_ao);
    cudaGetSymbolAddress((void**)&mid, g_mid);

    embed_kernel<<<Mtok, 256>>>(x, tok, h);

    dim3 gDD(Dn/TBN,  Mtok/TBM);   // 8 x 32
    dim3 gDF(FFn/TBN, Mtok/TBM);   // 32 x 32
    dim3 gDV(Vn/TBN,  Mtok/TBM);   // 250 x 32

    for (int l = 0; l < Ln; l++) {
        // attn LN
        ln_kernel<<<Mtok, 256>>>(h, ln_g + (size_t)(l*3+0)*Dn, ln_b + (size_t)(l*3+0)*Dn,
                                 nullptr, nullptr, ln, 0);
        // QKV projections
        tgemm_kernel<<<gDD, 256>>>(ln, Wqkv + (size_t)(l*3+0)*Dn*Dn,
                                   bqkv + (size_t)(l*3+0)*Dn, nullptr, q, Mtok, Dn, Dn, 0);
        tgemm_kernel<<<gDD, 256>>>(ln, Wqkv + (size_t)(l*3+1)*Dn*Dn,
                                   bqkv + (size_t)(l*3+1)*Dn, nullptr, k, Mtok, Dn, Dn, 0);
        tgemm_kernel<<<gDD, 256>>>(ln, Wqkv + (size_t)(l*3+2)*Dn*Dn,
                                   bqkv + (size_t)(l*3+2)*Dn, nullptr, v, Mtok, Dn, Dn, 0);
        // attention
        qk_kernel<<<dim3(Sn/64, Sn/64, Bn*Hn), 256>>>(q, k, rel, sc);
        softmax_kernel<<<dim3(Sn, Bn*Hn), 256>>>(sc);
        av_kernel<<<dim3(Sn/64, Bn*Hn), 256>>>(sc, v, ao);
        // output proj + residual
        tgemm_kernel<<<gDD, 256>>>(ao, Wo + (size_t)l*Dn*Dn, bo + (size_t)l*Dn,
                                   h, h, Mtok, Dn, Dn, 0);
        // ln2 then ffn-LN (fused)
        ln_kernel<<<Mtok, 256>>>(h, ln_g + (size_t)(l*3+1)*Dn, ln_b + (size_t)(l*3+1)*Dn,
                                 ln_g + (size_t)(l*3+2)*Dn, ln_b + (size_t)(l*3+2)*Dn, ln, 1);
        // FFN
        tgemm_kernel<<<gDF, 256>>>(ln, W1 + (size_t)l*Dn*FFn, b1 + (size_t)l*FFn,
                                   nullptr, mid, Mtok, FFn, Dn, 1);
        tgemm_kernel<<<gDD, 256>>>(mid, W2 + (size_t)l*FFn*Dn, b2 + (size_t)l*Dn,
                                   h, h, Mtok, Dn, FFn, 0);
    }

    ln_kernel<<<Mtok, 256>>>(h, lnf_g, lnf_b, nullptr, nullptr, ln, 0);
    tgemm_kernel<<<gDV, 256>>>(ln, Whead, bhead, nullptr, out, Mtok, Vn, Dn, 0);
}

// round 3
// speedup vs baseline: 2.4925x; 1.2609x over previous
#include <cuda_runtime.h>
#include <cuda_bf16.h>
#include <math.h>
#include <stdint.h>

// ---------------- problem constants ----------------
#define Bn   2
#define Sn   2048
#define Dn   1024
#define Hn   8
#define HDn  128
#define Vn   32000
#define Ln   6
#define Mtok (Bn*Sn)      // 4096
#define FFn  (4*Dn)       // 4096
#define SCALE_ 0.08838834764831845f   // 128^-0.5

// ---------------- scratch (device globals; no cudaMalloc allowed) ----------------
__device__ float g_h  [(size_t)Mtok*Dn];
__device__ float g_ln [(size_t)Mtok*Dn];
__device__ float g_qkv[(size_t)3*Mtok*Dn];
__device__ float g_sc [(size_t)Bn*Hn*Sn*Sn];   // 256 MB scores
__device__ float g_ao [(size_t)Mtok*Dn];
__device__ float g_mid[(size_t)Mtok*FFn];

// ---------------- helpers ----------------
__device__ __forceinline__ uint32_t f2tf32(float f) {
    uint32_t u;
    asm("cvt.rna.tf32.f32 %0, %1;" : "=r"(u) : "f"(f));
    return u;
}
__device__ __forceinline__ float tfv(float f) { return __uint_as_float(f2tf32(f)); }

// split f0,f1 into bf16 hi/lo pairs packed as b32 (low half = first element)
__device__ __forceinline__ void cvt_pair(float f0, float f1, uint32_t& hi, uint32_t& lo) {
    __nv_bfloat16 h0 = __float2bfloat16(f0);
    __nv_bfloat16 h1 = __float2bfloat16(f1);
    __nv_bfloat16 l0 = __float2bfloat16(f0 - __bfloat162float(h0));
    __nv_bfloat16 l1 = __float2bfloat16(f1 - __bfloat162float(h1));
    hi = ((uint32_t)__bfloat16_as_ushort(h1) << 16) | (uint32_t)__bfloat16_as_ushort(h0);
    lo = ((uint32_t)__bfloat16_as_ushort(l1) << 16) | (uint32_t)__bfloat16_as_ushort(l0);
}

#define MMA_BF16(C, A0,A1,A2,A3, B0,B1) \
    asm volatile("mma.sync.aligned.m16n8k16.row.col.f32.bf16.bf16.f32 " \
        "{%0,%1,%2,%3}, {%4,%5,%6,%7}, {%8,%9}, {%0,%1,%2,%3};" \
        : "+f"((C)[0]), "+f"((C)[1]), "+f"((C)[2]), "+f"((C)[3]) \
        : "r"(A0), "r"(A1), "r"(A2), "r"(A3), "r"(B0), "r"(B1))

__device__ __forceinline__ float blockReduceSum(float v, float* sm) {
    int lane = threadIdx.x & 31, wid = threadIdx.x >> 5;
    #pragma unroll
    for (int o = 16; o > 0; o >>= 1) v += __shfl_xor_sync(0xffffffffu, v, o);
    if (lane == 0) sm[wid] = v;
    __syncthreads();
    if (threadIdx.x < 32) {
        float t = (threadIdx.x < 8) ? sm[threadIdx.x] : 0.f;
        #pragma unroll
        for (int o = 4; o > 0; o >>= 1) t += __shfl_xor_sync(0xffffffffu, t, o);
        if (threadIdx.x == 0) sm[0] = t;
    }
    __syncthreads();
    float r = sm[0];
    __syncthreads();
    return r;
}

__device__ __forceinline__ float blockReduceMax(float v, float* sm) {
    int lane = threadIdx.x & 31, wid = threadIdx.x >> 5;
    #pragma unroll
    for (int o = 16; o > 0; o >>= 1) v = fmaxf(v, __shfl_xor_sync(0xffffffffu, v, o));
    if (lane == 0) sm[wid] = v;
    __syncthreads();
    if (threadIdx.x < 32) {
        float t = (threadIdx.x < 8) ? sm[threadIdx.x] : -INFINITY;
        #pragma unroll
        for (int o = 4; o > 0; o >>= 1) t = fmaxf(t, __shfl_xor_sync(0xffffffffu, t, o));
        if (threadIdx.x == 0) sm[0] = t;
    }
    __syncthreads();
    float r = sm[0];
    __syncthreads();
    return r;
}

// ---------------- embedding gather ----------------
__global__ void embed_kernel(const int* __restrict__ x,
                             const float* __restrict__ emb,
                             float* __restrict__ h) {
    int t = blockIdx.x;
    int tok = x[t];
    ((float4*)(h + (size_t)t*Dn))[threadIdx.x] =
        ((const float4*)(emb + (size_t)tok*Dn))[threadIdx.x];
}

// ---------------- LayerNorm (optionally two LNs fused) ----------------
__global__ __launch_bounds__(256)
void ln_kernel(const float* __restrict__ x,
               const float* __restrict__ g,  const float* __restrict__ b,
               const float* __restrict__ g2, const float* __restrict__ b2,
               float* __restrict__ y, int dbl) {
    __shared__ float sm[32];
    int row = blockIdx.x;
    float4 v = ((const float4*)(x + (size_t)row*Dn))[threadIdx.x];
    float s  = v.x + v.y + v.z + v.w;
    float ss = v.x*v.x + v.y*v.y + v.z*v.z + v.w*v.w;
    float sum   = blockReduceSum(s, sm);
    float sumsq = blockReduceSum(ss, sm);
    float mean = sum * (1.f/Dn);
    float var  = sumsq * (1.f/Dn) - mean*mean;
    float r = rsqrtf(var + 1e-5f);
    int c = threadIdx.x * 4;
    float4 gv = *(const float4*)(g + c);
    float4 bv = *(const float4*)(b + c);
    float4 o;
    o.x = (v.x - mean)*r*gv.x + bv.x;
    o.y = (v.y - mean)*r*gv.y + bv.y;
    o.z = (v.z - mean)*r*gv.z + bv.z;
    o.w = (v.w - mean)*r*gv.w + bv.w;
    if (dbl) {
        s  = o.x + o.y + o.z + o.w;
        ss = o.x*o.x + o.y*o.y + o.z*o.z + o.w*o.w;
        sum   = blockReduceSum(s, sm);
        sumsq = blockReduceSum(ss, sm);
        mean = sum * (1.f/Dn);
        var  = sumsq * (1.f/Dn) - mean*mean;
        r = rsqrtf(var + 1e-5f);
        float4 g2v = *(const float4*)(g2 + c);
        float4 b2v = *(const float4*)(b2 + c);
        o.x = (o.x - mean)*r*g2v.x + b2v.x;
        o.y = (o.y - mean)*r*g2v.y + b2v.y;
        o.z = (o.z - mean)*r*g2v.z + b2v.z;
        o.w = (o.w - mean)*r*g2v.w + b2v.w;
    }
    ((float4*)(y + (size_t)row*Dn))[threadIdx.x] = o;
}

// ---------------- TF32 tensor-core GEMM, double-buffered ----------------
#define TBM 128
#define TBN 128
#define TBK 16
#define APAD 136

__device__ __forceinline__ void tg_stage(float (*As)[APAD], float (*Bs)[APAD],
                                         int arow0, int acol0, int brl, int bcl,
                                         const float4& a0, const float4& a1,
                                         const float4& b0, const float4& b1) {
    As[acol0+0][arow0]    = tfv(a0.x);
    As[acol0+1][arow0]    = tfv(a0.y);
    As[acol0+2][arow0]    = tfv(a0.z);
    As[acol0+3][arow0]    = tfv(a0.w);
    As[acol0+0][arow0+64] = tfv(a1.x);
    As[acol0+1][arow0+64] = tfv(a1.y);
    As[acol0+2][arow0+64] = tfv(a1.z);
    As[acol0+3][arow0+64] = tfv(a1.w);
    float4 tb0 = make_float4(tfv(b0.x), tfv(b0.y), tfv(b0.z), tfv(b0.w));
    float4 tb1 = make_float4(tfv(b1.x), tfv(b1.y), tfv(b1.z), tfv(b1.w));
    *(float4*)&Bs[brl][bcl]   = tb0;
    *(float4*)&Bs[brl+8][bcl] = tb1;
}

__global__ __launch_bounds__(256, 2)
void tgemm_kernel(const float* __restrict__ A, const float* __restrict__ B,
                  const float* __restrict__ bias, const float* __restrict__ add,
                  float* __restrict__ C, int M, int N, int K, int relu,
                  size_t zB, size_t zBias, size_t zC) {
    __shared__ float As[2][TBK][APAD];
    __shared__ float Bs[2][TBK][APAD];

    B += (size_t)blockIdx.z * zB;
    if (bias) bias += (size_t)blockIdx.z * zBias;
    C += (size_t)blockIdx.z * zC;

    int tid  = threadIdx.x;
    int brow = blockIdx.y * TBM;
    int bcol = blockIdx.x * TBN;

    int warp = tid >> 5, lane = tid & 31;
    int gid = lane >> 2, tig = lane & 3;
    int warpM = (warp >> 2) * 64;
    int warpN = (warp & 3) * 32;

    int arow0 = tid >> 2;
    int acol0 = (tid & 3) << 2;
    int brl   = tid >> 5;
    int bcl   = (tid & 31) << 2;

    const float* Ap = A + (size_t)brow * K;
    const float* Bp = B + bcol;

    float4 a0 = *(const float4*)(Ap + (size_t)arow0      * K + acol0);
    float4 a1 = *(const float4*)(Ap + (size_t)(arow0+64) * K + acol0);
    float4 b0 = *(const float4*)(Bp + (size_t)brl     * N + bcl);
    float4 b1 = *(const float4*)(Bp + (size_t)(brl+8) * N + bcl);

    tg_stage(As[0], Bs[0], arow0, acol0, brl, bcl, a0, a1, b0, b1);
    __syncthreads();

    float acc[4][4][4] = {};
    int p = 0;

    for (int k0 = 0; k0 < K; k0 += TBK) {
        bool nxt = (k0 + TBK) < K;
        if (nxt) {
            const float* An  = Ap + (k0 + TBK);
            const float* Bnp = Bp + (size_t)(k0 + TBK) * N;
            a0 = *(const float4*)(An + (size_t)arow0      * K + acol0);
            a1 = *(const float4*)(An + (size_t)(arow0+64) * K + acol0);
            b0 = *(const float4*)(Bnp + (size_t)brl     * N + bcl);
            b1 = *(const float4*)(Bnp + (size_t)(brl+8) * N + bcl);
        }
        float (*Asp)[APAD] = As[p];
        float (*Bsp)[APAD] = Bs[p];
        #pragma unroll
        for (int ks = 0; ks < 2; ks++) {
            int kb = ks * 8;
            uint32_t af[4][4], bf[4][2];
            #pragma unroll
            for (int mt = 0; mt < 4; mt++) {
                int r = warpM + mt*16 + gid;
                af[mt][0] = __float_as_uint(Asp[kb+tig  ][r]);
                af[mt][1] = __float_as_uint(Asp[kb+tig  ][r+8]);
                af[mt][2] = __float_as_uint(Asp[kb+tig+4][r]);
                af[mt][3] = __float_as_uint(Asp[kb+tig+4][r+8]);
            }
            #pragma unroll
            for (int nt = 0; nt < 4; nt++) {
                int c = warpN + nt*8 + gid;
                bf[nt][0] = __float_as_uint(Bsp[kb+tig  ][c]);
                bf[nt][1] = __float_as_uint(Bsp[kb+tig+4][c]);
            }
            #pragma unroll
            for (int mt = 0; mt < 4; mt++)
                #pragma unroll
                for (int nt = 0; nt < 4; nt++) {
                    asm volatile(
                        "mma.sync.aligned.m16n8k8.row.col.f32.tf32.tf32.f32 "
                        "{%0,%1,%2,%3}, {%4,%5,%6,%7}, {%8,%9}, {%0,%1,%2,%3};\n"
                        : "+f"(acc[mt][nt][0]), "+f"(acc[mt][nt][1]),
                          "+f"(acc[mt][nt][2]), "+f"(acc[mt][nt][3])
                        : "r"(af[mt][0]), "r"(af[mt][1]), "r"(af[mt][2]), "r"(af[mt][3]),
                          "r"(bf[nt][0]), "r"(bf[nt][1]));
                }
        }
        if (nxt) tg_stage(As[p^1], Bs[p^1], arow0, acol0, brl, bcl, a0, a1, b0, b1);
        __syncthreads();
        p ^= 1;
    }

    #pragma unroll
    for (int mt = 0; mt < 4; mt++) {
        int r0 = brow + warpM + mt*16 + gid;
        int r1 = r0 + 8;
        #pragma unroll
        for (int nt = 0; nt < 4; nt++) {
            int c = bcol + warpN + nt*8 + tig*2;
            float v00 = acc[mt][nt][0], v01 = acc[mt][nt][1];
            float v10 = acc[mt][nt][2], v11 = acc[mt][nt][3];
            if (bias) {
                float bb0 = bias[c], bb1 = bias[c+1];
                v00 += bb0; v01 += bb1; v10 += bb0; v11 += bb1;
            }
            if (relu) {
                v00 = fmaxf(v00, 0.f); v01 = fmaxf(v01, 0.f);
                v10 = fmaxf(v10, 0.f); v11 = fmaxf(v11, 0.f);
            }
            if (add) {
                const float* ad0 = add + (size_t)r0*N + c;
                const float* ad1 = add + (size_t)r1*N + c;
                v00 += ad0[0]; v01 += ad0[1];
                v10 += ad1[0]; v11 += ad1[1];
            }
            *(float2*)(C + (size_t)r0*N + c) = make_float2(v00, v01);
            *(float2*)(C + (size_t)r1*N + c) = make_float2(v10, v11);
        }
    }
}

// ---------------- rel-pos bias + causal mask (same math as fp32 version) ----------------
__device__ __forceinline__ float qk_maskbias(float acc, int i, int j,
                                             const float* __restrict__ rel, int h,
                                             float inv_log8) {
    if (j > i) return -INFINITY;
    int n = i - j;
    int bucket;
    if (n < 16) bucket = n;
    else {
        int vb = 16 + (int)((logf((float)n * (1.0f/16.0f)) * inv_log8) * 16.0f);
        bucket = vb < 31 ? vb : 31;
    }
    return (acc + rel[bucket*Hn + h]*SCALE_) * SCALE_;
}

// ---------------- QK^T on tensor cores (3x bf16 compensated) ----------------
__global__ __launch_bounds__(256)
void qk_tc_kernel(const float* __restrict__ q, const float* __restrict__ k,
                  const float* __restrict__ rel, float* __restrict__ scores) {
    int ti = blockIdx.y, tj = blockIdx.x;
    if (tj > ti) return;
    int bh = blockIdx.z, b = bh >> 3, h = bh & 7;
    __shared__ uint16_t qh[64][72], ql[64][72], kh[64][72], kl[64][72];
    int tid = threadIdx.x;
    int warp = tid >> 5, lane = tid & 31;
    int g = lane >> 2, t = lane & 3;
    int warpM = (warp & 3) << 4;      // 0..48
    int warpN = (warp >> 2) << 5;     // 0, 32
    const float* qb = q + ((size_t)b*Sn + ti*64)*Dn + h*HDn;
    const float* kb = k + ((size_t)b*Sn + tj*64)*Dn + h*HDn;
    float acc[4][4] = {};   // [nt][c0..c3]

    for (int half = 0; half < 2; half++) {
        if (half) __syncthreads();
        int d0 = half * 64;
        for (int e = tid; e < 64*16; e += 256) {
            int row = e >> 4;
            int c4  = (e & 15) << 2;
            float4 qv = *(const float4*)(qb + (size_t)row*Dn + d0 + c4);
            float4 kv = *(const float4*)(kb + (size_t)row*Dn + d0 + c4);
            uint32_t hi0, lo0, hi1, lo1;
            cvt_pair(qv.x, qv.y, hi0, lo0);
            cvt_pair(qv.z, qv.w, hi1, lo1);
            *(uint32_t*)&qh[row][c4]   = hi0; *(uint32_t*)&qh[row][c4+2] = hi1;
            *(uint32_t*)&ql[row][c4]   = lo0; *(uint32_t*)&ql[row][c4+2] = lo1;
            cvt_pair(kv.x, kv.y, hi0, lo0);
            cvt_pair(kv.z, kv.w, hi1, lo1);
            *(uint32_t*)&kh[row][c4]   = hi0; *(uint32_t*)&kh[row][c4+2] = hi1;
            *(uint32_t*)&kl[row][c4]   = lo0; *(uint32_t*)&kl[row][c4+2] = lo1;
        }
        __syncthreads();
        #pragma unroll
        for (int ks = 0; ks < 4; ks++) {
            int kw = ks*16 + 2*t;
            int rA = warpM + g;
            uint32_t ah0 = *(const uint32_t*)&qh[rA  ][kw];
            uint32_t ah1 = *(const uint32_t*)&qh[rA+8][kw];
            uint32_t ah2 = *(const uint32_t*)&qh[rA  ][kw+8];
            uint32_t ah3 = *(const uint32_t*)&qh[rA+8][kw+8];
            uint32_t al0 = *(const uint32_t*)&ql[rA  ][kw];
            uint32_t al1 = *(const uint32_t*)&ql[rA+8][kw];
            uint32_t al2 = *(const uint32_t*)&ql[rA  ][kw+8];
            uint32_t al3 = *(const uint32_t*)&ql[rA+8][kw+8];
            #pragma unroll
            for (int nt = 0; nt < 4; nt++) {
                int rB = warpN + nt*8 + g;
                uint32_t bh0 = *(const uint32_t*)&kh[rB][kw];
                uint32_t bh1 = *(const uint32_t*)&kh[rB][kw+8];
                uint32_t bl0 = *(const uint32_t*)&kl[rB][kw];
                uint32_t bl1 = *(const uint32_t*)&kl[rB][kw+8];
                MMA_BF16(acc[nt], ah0, ah1, ah2, ah3, bh0, bh1);
                MMA_BF16(acc[nt], ah0, ah1, ah2, ah3, bl0, bl1);
                MMA_BF16(acc[nt], al0, al1, al2, al3, bh0, bh1);
            }
        }
    }

    float* sb = scores + (size_t)bh*Sn*Sn;
    float inv_log8 = 1.0f / logf(8.0f);
    #pragma unroll
    for (int nt = 0; nt < 4; nt++) {
        #pragma unroll
        for (int rr = 0; rr < 2; rr++) {
            int i  = ti*64 + warpM + g + rr*8;
            int j0 = tj*64 + warpN + nt*8 + 2*t;
            float o0 = qk_maskbias(acc[nt][rr*2+0], i, j0,   rel, h, inv_log8);
            float o1 = qk_maskbias(acc[nt][rr*2+1], i, j0+1, rel, h, inv_log8);
            *(float2*)&sb[(size_t)i*Sn + j0] = make_float2(o0, o1);
        }
    }
}

// ---------------- causal row softmax (+zero-pad diagonal tile) ----------------
__global__ __launch_bounds__(256)
void softmax_kernel(float* __restrict__ scores) {
    __shared__ float sm[32];
    int i = blockIdx.x, bh = blockIdx.y;
    float* row = scores + ((size_t)bh*Sn + i)*Sn;
    int len = i + 1;
    float m = -INFINITY;
    for (int j = threadIdx.x; j < len; j += 256) m = fmaxf(m, row[j]);
    m = blockReduceMax(m, sm);
    float s = 0.f;
    for (int j = threadIdx.x; j < len; j += 256) {
        float e = __expf(row[j] - m);
        row[j] = e;
        s += e;
    }
    float sum = blockReduceSum(s, sm);
    float inv = 1.f / sum;
    for (int j = threadIdx.x; j < len; j += 256) row[j] *= inv;
    int pad = ((i >> 6) + 1) << 6;
    if (pad > Sn) pad = Sn;
    for (int j = len + threadIdx.x; j < pad; j += 256) row[j] = 0.f;
}

// ---------------- AV on tensor cores (3x bf16 compensated) ----------------
// smem layout (uint16): phi[64][72], plo[64][72], vhT[128][74], vlT[128][74]
#define AV_SMEM_BYTES ((64*72*2 + 128*74*2) * 2)

__global__ __launch_bounds__(256)
void av_tc_kernel(const float* __restrict__ scores, const float* __restrict__ v,
                  float* __restrict__ out) {
    extern __shared__ uint16_t sm_[];
    uint16_t (*phi)[72] = (uint16_t(*)[72])(sm_);
    uint16_t (*plo)[72] = (uint16_t(*)[72])(sm_ + 64*72);
    uint16_t (*vhT)[74] = (uint16_t(*)[74])(sm_ + 2*64*72);
    uint16_t (*vlT)[74] = (uint16_t(*)[74])(sm_ + 2*64*72 + 128*74);

    int ti = blockIdx.x;
    int bh = blockIdx.y, b = bh >> 3, h = bh & 7;
    int tid = threadIdx.x;
    int warp = tid >> 5, lane = tid & 31;
    int g = lane >> 2, t = lane & 3;
    int warpM = (warp & 3) << 4;      // 0..48
    int warpN = (warp >> 2) << 6;     // 0, 64
    const float* sb = scores + ((size_t)bh*Sn + (size_t)ti*64)*Sn;
    const float* vb = v + ((size_t)b*Sn)*Dn + h*HDn;

    float acc[8][4] = {};   // [nt over 64 cols][c0..c3]

    for (int jt = 0; jt <= ti; jt++) {
        if (jt) __syncthreads();
        // stage P tile 64x64 (hi/lo, pairs along kv)
        for (int e = tid; e < 64*16; e += 256) {
            int row = e >> 4;
            int c4  = (e & 15) << 2;
            float4 pv = *(const float4*)(sb + (size_t)row*Sn + jt*64 + c4);
            uint32_t hi0, lo0, hi1, lo1;
            cvt_pair(pv.x, pv.y, hi0, lo0);
            cvt_pair(pv.z, pv.w, hi1, lo1);
            *(uint32_t*)&phi[row][c4]   = hi0; *(uint32_t*)&phi[row][c4+2] = hi1;
            *(uint32_t*)&plo[row][c4]   = lo0; *(uint32_t*)&plo[row][c4+2] = lo1;
        }
        // stage V tile transposed: vhT[hd][kv] (hi/lo, pairs along kv)
        {
            int hd  = tid & 127;
            int kvb = (tid >> 7) * 32;
            #pragma unroll
            for (int r = 0; r < 8; r++) {
                int kv4 = kvb + r*4;
                const float* vp = vb + (size_t)(jt*64 + kv4)*Dn + hd;
                float f0 = vp[0];
                float f1 = vp[(size_t)Dn];
                float f2 = vp[(size_t)2*Dn];
                float f3 = vp[(size_t)3*Dn];
                uint32_t hi0, lo0, hi1, lo1;
                cvt_pair(f0, f1, hi0, lo0);
                cvt_pair(f2, f3, hi1, lo1);
                *(uint32_t*)&vhT[hd][kv4]   = hi0; *(uint32_t*)&vhT[hd][kv4+2] = hi1;
                *(uint32_t*)&vlT[hd][kv4]   = lo0; *(uint32_t*)&vlT[hd][kv4+2] = lo1;
            }
        }
        __syncthreads();
        #pragma unroll
        for (int ks = 0; ks < 4; ks++) {
            int kw = ks*16 + 2*t;
            int rA = warpM + g;
            uint32_t ah0 = *(const uint32_t*)&phi[rA  ][kw];
            uint32_t ah1 = *(const uint32_t*)&phi[rA+8][kw];
            uint32_t ah2 = *(const uint32_t*)&phi[rA  ][kw+8];
            uint32_t ah3 = *(const uint32_t*)&phi[rA+8][kw+8];
            uint32_t al0 = *(const uint32_t*)&plo[rA  ][kw];
            uint32_t al1 = *(const uint32_t*)&plo[rA+8][kw];
            uint32_t al2 = *(const uint32_t*)&plo[rA  ][kw+8];
            uint32_t al3 = *(const uint32_t*)&plo[rA+8][kw+8];
            #pragma unroll
            for (int nt = 0; nt < 8; nt++) {
                int rB = warpN + nt*8 + g;
                uint32_t bh0 = *(const uint32_t*)&vhT[rB][kw];
                uint32_t bh1 = *(const uint32_t*)&vhT[rB][kw+8];
                uint32_t bl0 = *(const uint32_t*)&vlT[rB][kw];
                uint32_t bl1 = *(const uint32_t*)&vlT[rB][kw+8];
                MMA_BF16(acc[nt], ah0, ah1, ah2, ah3, bh0, bh1);
                MMA_BF16(acc[nt], ah0, ah1, ah2, ah3, bl0, bl1);
                MMA_BF16(acc[nt], al0, al1, al2, al3, bh0, bh1);
            }
        }
    }

    #pragma unroll
    for (int nt = 0; nt < 8; nt++) {
        #pragma unroll
        for (int rr = 0; rr < 2; rr++) {
            int i   = ti*64 + warpM + g + rr*8;
            int col = warpN + nt*8 + 2*t;
            float* op = out + ((size_t)b*Sn + i)*Dn + h*HDn + col;
            *(float2*)op = make_float2(acc[nt][rr*2+0], acc[nt][rr*2+1]);
        }
    }
}

// ---------------- orchestration ----------------
extern "C" void kernel_launch(void* const* d_in, const int* in_sizes, int n_in,
                              void* d_out, int out_size) {
    (void)in_sizes; (void)n_in; (void)out_size;
    const int*   x     = (const int*)  d_in[0];
    const float* tok   = (const float*)d_in[1];
    const float* rel   = (const float*)d_in[2];
    const float* ln_g  = (const float*)d_in[3];
    const float* ln_b  = (const float*)d_in[4];
    const float* Wqkv  = (const float*)d_in[5];
    const float* bqkv  = (const float*)d_in[6];
    const float* Wo    = (const float*)d_in[7];
    const float* bo    = (const float*)d_in[8];
    const float* W1    = (const float*)d_in[9];
    const float* b1    = (const float*)d_in[10];
    const float* W2    = (const float*)d_in[11];
    const float* b2    = (const float*)d_in[12];
    const float* lnf_g = (const float*)d_in[13];
    const float* lnf_b = (const float*)d_in[14];
    const float* Whead = (const float*)d_in[15];
    const float* bhead = (const float*)d_in[16];
    float* out = (float*)d_out;

    float *h, *ln, *qkv, *sc, *ao, *mid;
    cudaGetSymbolAddress((void**)&h,   g_h);
    cudaGetSymbolAddress((void**)&ln,  g_ln);
    cudaGetSymbolAddress((void**)&qkv, g_qkv);
    cudaGetSymbolAddress((void**)&sc,  g_sc);
    cudaGetSymbolAddress((void**)&ao,  g_ao);
    cudaGetSymbolAddress((void**)&mid, g_mid);

    cudaFuncSetAttribute(av_tc_kernel, cudaFuncAttributeMaxDynamicSharedMemorySize,
                         AV_SMEM_BYTES);

    const float* q = qkv;
    const float* k = qkv + (size_t)Mtok*Dn;
    const float* v = qkv + (size_t)2*Mtok*Dn;

    embed_kernel<<<Mtok, 256>>>(x, tok, h);

    dim3 gDD(Dn/TBN,  Mtok/TBM);       // 8 x 32
    dim3 gQKV(Dn/TBN, Mtok/TBM, 3);    // batched QKV
    dim3 gDF(FFn/TBN, Mtok/TBM);       // 32 x 32
    dim3 gDV(Vn/TBN,  Mtok/TBM);       // 250 x 32

    for (int l = 0; l < Ln; l++) {
        // attn LN
        ln_kernel<<<Mtok, 256>>>(h, ln_g + (size_t)(l*3+0)*Dn, ln_b + (size_t)(l*3+0)*Dn,
                                 nullptr, nullptr, ln, 0);
        // QKV projections (batched over z)
        tgemm_kernel<<<gQKV, 256>>>(ln, Wqkv + (size_t)l*3*Dn*Dn,
                                    bqkv + (size_t)l*3*Dn, nullptr, qkv,
                                    Mtok, Dn, Dn, 0,
                                    (size_t)Dn*Dn, (size_t)Dn, (size_t)Mtok*Dn);
        // attention
        qk_tc_kernel<<<dim3(Sn/64, Sn/64, Bn*Hn), 256>>>(q, k, rel, sc);
        softmax_kernel<<<dim3(Sn, Bn*Hn), 256>>>(sc);
        av_tc_kernel<<<dim3(Sn/64, Bn*Hn), 256, AV_SMEM_BYTES>>>(sc, v, ao);
        // output proj + residual
        tgemm_kernel<<<gDD, 256>>>(ao, Wo + (size_t)l*Dn*Dn, bo + (size_t)l*Dn,
                                   h, h, Mtok, Dn, Dn, 0, 0, 0, 0);
        // ln2 then ffn-LN (fused)
        ln_kernel<<<Mtok, 256>>>(h, ln_g + (size_t)(l*3+1)*Dn, ln_b + (size_t)(l*3+1)*Dn,
                                 ln_g + (size_t)(l*3+2)*Dn, ln_b + (size_t)(l*3+2)*Dn, ln, 1);
        // FFN
        tgemm_kernel<<<gDF, 256>>>(ln, W1 + (size_t)l*Dn*FFn, b1 + (size_t)l*FFn,
                                   nullptr, mid, Mtok, FFn, Dn, 1, 0, 0, 0);
        tgemm_kernel<<<gDD, 256>>>(mid, W2 + (size_t)l*FFn*Dn, b2 + (size_t)l*Dn,
                                   h, h, Mtok, Dn, FFn, 0, 0, 0, 0);
    }

    ln_kernel<<<Mtok, 256>>>(h, lnf_g, lnf_b, nullptr, nullptr, ln, 0);
    tgemm_kernel<<<gDV, 256>>>(ln, Whead, bhead, nullptr, out, Mtok, Vn, Dn, 0, 0, 0, 0);
}

// round 4
// speedup vs baseline: 2.7237x; 1.0927x over previous
#include <cuda_runtime.h>
#include <cuda_bf16.h>
#include <math.h>
#include <stdint.h>

// ---------------- problem constants ----------------
#define Bn   2
#define Sn   2048
#define Dn   1024
#define Hn   8
#define HDn  128
#define Vn   32000
#define Ln   6
#define Mtok (Bn*Sn)      // 4096
#define FFn  (4*Dn)       // 4096
#define SCALE_ 0.08838834764831845f   // 128^-0.5

// ---------------- scratch (device globals; no cudaMalloc allowed) ----------------
__device__ float g_h  [(size_t)Mtok*Dn];
__device__ float g_ln [(size_t)Mtok*Dn];
__device__ float g_qkv[(size_t)3*Mtok*Dn];
__device__ float g_ao [(size_t)Mtok*Dn];
__device__ float g_mid[(size_t)Mtok*FFn];
// converted attention operands (bf16 hi/lo packed as u32 pairs)
__device__ uint32_t g_qh2[(size_t)Bn*Hn*Sn*64];
__device__ uint32_t g_ql2[(size_t)Bn*Hn*Sn*64];
__device__ uint32_t g_kh2[(size_t)Bn*Hn*Sn*64];
__device__ uint32_t g_kl2[(size_t)Bn*Hn*Sn*64];
__device__ uint32_t g_vh2T[(size_t)Bn*Hn*HDn*(Sn/2)];
__device__ uint32_t g_vl2T[(size_t)Bn*Hn*HDn*(Sn/2)];
__device__ float g_biasn[Hn*Sn];

// ---------------- helpers ----------------
__device__ __forceinline__ uint32_t f2tf32(float f) {
    uint32_t u;
    asm("cvt.rna.tf32.f32 %0, %1;" : "=r"(u) : "f"(f));
    return u;
}
__device__ __forceinline__ float tfv(float f) { return __uint_as_float(f2tf32(f)); }

// split f0,f1 into bf16 hi/lo pairs packed as b32 (low half = first element)
__device__ __forceinline__ void cvt_pair(float f0, float f1, uint32_t& hi, uint32_t& lo) {
    __nv_bfloat16 h0 = __float2bfloat16(f0);
    __nv_bfloat16 h1 = __float2bfloat16(f1);
    __nv_bfloat16 l0 = __float2bfloat16(f0 - __bfloat162float(h0));
    __nv_bfloat16 l1 = __float2bfloat16(f1 - __bfloat162float(h1));
    hi = ((uint32_t)__bfloat16_as_ushort(h1) << 16) | (uint32_t)__bfloat16_as_ushort(h0);
    lo = ((uint32_t)__bfloat16_as_ushort(l1) << 16) | (uint32_t)__bfloat16_as_ushort(l0);
}

#define MMA_BF16(C, A0,A1,A2,A3, B0,B1) \
    asm volatile("mma.sync.aligned.m16n8k16.row.col.f32.bf16.bf16.f32 " \
        "{%0,%1,%2,%3}, {%4,%5,%6,%7}, {%8,%9}, {%0,%1,%2,%3};" \
        : "+f"((C)[0]), "+f"((C)[1]), "+f"((C)[2]), "+f"((C)[3]) \
        : "r"(A0), "r"(A1), "r"(A2), "r"(A3), "r"(B0), "r"(B1))

__device__ __forceinline__ float blockReduceSum(float v, float* sm) {
    int lane = threadIdx.x & 31, wid = threadIdx.x >> 5;
    #pragma unroll
    for (int o = 16; o > 0; o >>= 1) v += __shfl_xor_sync(0xffffffffu, v, o);
    if (lane == 0) sm[wid] = v;
    __syncthreads();
    if (threadIdx.x < 32) {
        float t = (threadIdx.x < 8) ? sm[threadIdx.x] : 0.f;
        #pragma unroll
        for (int o = 4; o > 0; o >>= 1) t += __shfl_xor_sync(0xffffffffu, t, o);
        if (threadIdx.x == 0) sm[0] = t;
    }
    __syncthreads();
    float r = sm[0];
    __syncthreads();
    return r;
}

// ---------------- embedding gather ----------------
__global__ void embed_kernel(const int* __restrict__ x,
                             const float* __restrict__ emb,
                             float* __restrict__ h) {
    int t = blockIdx.x;
    int tok = x[t];
    ((float4*)(h + (size_t)t*Dn))[threadIdx.x] =
        ((const float4*)(emb + (size_t)tok*Dn))[threadIdx.x];
}

// ---------------- LayerNorm (optionally two LNs fused) ----------------
__global__ __launch_bounds__(256)
void ln_kernel(const float* __restrict__ x,
               const float* __restrict__ g,  const float* __restrict__ b,
               const float* __restrict__ g2, const float* __restrict__ b2,
               float* __restrict__ y, int dbl) {
    __shared__ float sm[32];
    int row = blockIdx.x;
    float4 v = ((const float4*)(x + (size_t)row*Dn))[threadIdx.x];
    float s  = v.x + v.y + v.z + v.w;
    float ss = v.x*v.x + v.y*v.y + v.z*v.z + v.w*v.w;
    float sum   = blockReduceSum(s, sm);
    float sumsq = blockReduceSum(ss, sm);
    float mean = sum * (1.f/Dn);
    float var  = sumsq * (1.f/Dn) - mean*mean;
    float r = rsqrtf(var + 1e-5f);
    int c = threadIdx.x * 4;
    float4 gv = *(const float4*)(g + c);
    float4 bv = *(const float4*)(b + c);
    float4 o;
    o.x = (v.x - mean)*r*gv.x + bv.x;
    o.y = (v.y - mean)*r*gv.y + bv.y;
    o.z = (v.z - mean)*r*gv.z + bv.z;
    o.w = (v.w - mean)*r*gv.w + bv.w;
    if (dbl) {
        s  = o.x + o.y + o.z + o.w;
        ss = o.x*o.x + o.y*o.y + o.z*o.z + o.w*o.w;
        sum   = blockReduceSum(s, sm);
        sumsq = blockReduceSum(ss, sm);
        mean = sum * (1.f/Dn);
        var  = sumsq * (1.f/Dn) - mean*mean;
        r = rsqrtf(var + 1e-5f);
        float4 g2v = *(const float4*)(g2 + c);
        float4 b2v = *(const float4*)(b2 + c);
        o.x = (o.x - mean)*r*g2v.x + b2v.x;
        o.y = (o.y - mean)*r*g2v.y + b2v.y;
        o.z = (o.z - mean)*r*g2v.z + b2v.z;
        o.w = (o.w - mean)*r*g2v.w + b2v.w;
    }
    ((float4*)(y + (size_t)row*Dn))[threadIdx.x] = o;
}

// ---------------- TF32 tensor-core GEMM, double-buffered ----------------
#define TBM 128
#define TBN 128
#define TBK 16
#define APAD 136

__device__ __forceinline__ void tg_stage(float (*As)[APAD], float (*Bs)[APAD],
                                         int arow0, int acol0, int brl, int bcl,
                                         const float4& a0, const float4& a1,
                                         const float4& b0, const float4& b1) {
    As[acol0+0][arow0]    = tfv(a0.x);
    As[acol0+1][arow0]    = tfv(a0.y);
    As[acol0+2][arow0]    = tfv(a0.z);
    As[acol0+3][arow0]    = tfv(a0.w);
    As[acol0+0][arow0+64] = tfv(a1.x);
    As[acol0+1][arow0+64] = tfv(a1.y);
    As[acol0+2][arow0+64] = tfv(a1.z);
    As[acol0+3][arow0+64] = tfv(a1.w);
    float4 tb0 = make_float4(tfv(b0.x), tfv(b0.y), tfv(b0.z), tfv(b0.w));
    float4 tb1 = make_float4(tfv(b1.x), tfv(b1.y), tfv(b1.z), tfv(b1.w));
    *(float4*)&Bs[brl][bcl]   = tb0;
    *(float4*)&Bs[brl+8][bcl] = tb1;
}

__global__ __launch_bounds__(256, 2)
void tgemm_kernel(const float* __restrict__ A, const float* __restrict__ B,
                  const float* __restrict__ bias, const float* __restrict__ add,
                  float* __restrict__ C, int M, int N, int K, int relu,
                  size_t zB, size_t zBias, size_t zC) {
    __shared__ float As[2][TBK][APAD];
    __shared__ float Bs[2][TBK][APAD];

    B += (size_t)blockIdx.z * zB;
    if (bias) bias += (size_t)blockIdx.z * zBias;
    C += (size_t)blockIdx.z * zC;

    int tid  = threadIdx.x;
    int brow = blockIdx.y * TBM;
    int bcol = blockIdx.x * TBN;

    int warp = tid >> 5, lane = tid & 31;
    int gid = lane >> 2, tig = lane & 3;
    int warpM = (warp >> 2) * 64;
    int warpN = (warp & 3) * 32;

    int arow0 = tid >> 2;
    int acol0 = (tid & 3) << 2;
    int brl   = tid >> 5;
    int bcl   = (tid & 31) << 2;

    const float* Ap = A + (size_t)brow * K;
    const float* Bp = B + bcol;

    float4 a0 = *(const float4*)(Ap + (size_t)arow0      * K + acol0);
    float4 a1 = *(const float4*)(Ap + (size_t)(arow0+64) * K + acol0);
    float4 b0 = *(const float4*)(Bp + (size_t)brl     * N + bcl);
    float4 b1 = *(const float4*)(Bp + (size_t)(brl+8) * N + bcl);

    tg_stage(As[0], Bs[0], arow0, acol0, brl, bcl, a0, a1, b0, b1);
    __syncthreads();

    float acc[4][4][4] = {};
    int p = 0;

    for (int k0 = 0; k0 < K; k0 += TBK) {
        bool nxt = (k0 + TBK) < K;
        if (nxt) {
            const float* An  = Ap + (k0 + TBK);
            const float* Bnp = Bp + (size_t)(k0 + TBK) * N;
            a0 = *(const float4*)(An + (size_t)arow0      * K + acol0);
            a1 = *(const float4*)(An + (size_t)(arow0+64) * K + acol0);
            b0 = *(const float4*)(Bnp + (size_t)brl     * N + bcl);
            b1 = *(const float4*)(Bnp + (size_t)(brl+8) * N + bcl);
        }
        float (*Asp)[APAD] = As[p];
        float (*Bsp)[APAD] = Bs[p];
        #pragma unroll
        for (int ks = 0; ks < 2; ks++) {
            int kb = ks * 8;
            uint32_t af[4][4], bf[4][2];
            #pragma unroll
            for (int mt = 0; mt < 4; mt++) {
                int r = warpM + mt*16 + gid;
                af[mt][0] = __float_as_uint(Asp[kb+tig  ][r]);
                af[mt][1] = __float_as_uint(Asp[kb+tig  ][r+8]);
                af[mt][2] = __float_as_uint(Asp[kb+tig+4][r]);
                af[mt][3] = __float_as_uint(Asp[kb+tig+4][r+8]);
            }
            #pragma unroll
            for (int nt = 0; nt < 4; nt++) {
                int c = warpN + nt*8 + gid;
                bf[nt][0] = __float_as_uint(Bsp[kb+tig  ][c]);
                bf[nt][1] = __float_as_uint(Bsp[kb+tig+4][c]);
            }
            #pragma unroll
            for (int mt = 0; mt < 4; mt++)
                #pragma unroll
                for (int nt = 0; nt < 4; nt++) {
                    asm volatile(
                        "mma.sync.aligned.m16n8k8.row.col.f32.tf32.tf32.f32 "
                        "{%0,%1,%2,%3}, {%4,%5,%6,%7}, {%8,%9}, {%0,%1,%2,%3};\n"
                        : "+f"(acc[mt][nt][0]), "+f"(acc[mt][nt][1]),
                          "+f"(acc[mt][nt][2]), "+f"(acc[mt][nt][3])
                        : "r"(af[mt][0]), "r"(af[mt][1]), "r"(af[mt][2]), "r"(af[mt][3]),
                          "r"(bf[nt][0]), "r"(bf[nt][1]));
                }
        }
        if (nxt) tg_stage(As[p^1], Bs[p^1], arow0, acol0, brl, bcl, a0, a1, b0, b1);
        __syncthreads();
        p ^= 1;
    }

    #pragma unroll
    for (int mt = 0; mt < 4; mt++) {
        int r0 = brow + warpM + mt*16 + gid;
        int r1 = r0 + 8;
        #pragma unroll
        for (int nt = 0; nt < 4; nt++) {
            int c = bcol + warpN + nt*8 + tig*2;
            float v00 = acc[mt][nt][0], v01 = acc[mt][nt][1];
            float v10 = acc[mt][nt][2], v11 = acc[mt][nt][3];
            if (bias) {
                float bb0 = bias[c], bb1 = bias[c+1];
                v00 += bb0; v01 += bb1; v10 += bb0; v11 += bb1;
            }
            if (relu) {
                v00 = fmaxf(v00, 0.f); v01 = fmaxf(v01, 0.f);
                v10 = fmaxf(v10, 0.f); v11 = fmaxf(v11, 0.f);
            }
            if (add) {
                const float* ad0 = add + (size_t)r0*N + c;
                const float* ad1 = add + (size_t)r1*N + c;
                v00 += ad0[0]; v01 += ad0[1];
                v10 += ad1[0]; v11 += ad1[1];
            }
            *(float2*)(C + (size_t)r0*N + c) = make_float2(v00, v01);
            *(float2*)(C + (size_t)r1*N + c) = make_float2(v10, v11);
        }
    }
}

// ---------------- rel-pos bias table (layer-invariant) ----------------
__global__ void bias_init_kernel(const float* __restrict__ rel,
                                 float* __restrict__ biasn) {
    int n = blockIdx.x * 256 + threadIdx.x;
    if (n >= Sn) return;
    float inv_log8 = 1.0f / logf(8.0f);
    int bucket;
    if (n < 16) bucket = n;
    else {
        int vb = 16 + (int)((logf((float)n * (1.0f/16.0f)) * inv_log8) * 16.0f);
        bucket = vb < 31 ? vb : 31;
    }
    for (int h = 0; h < Hn; h++)
        biasn[h*Sn + n] = rel[bucket*Hn + h] * SCALE_;
}

// ---------------- convert Q,K to packed bf16 hi/lo (pairs along hd) ----------------
__global__ __launch_bounds__(256)
void cvt_qk_kernel(const float* __restrict__ q, const float* __restrict__ k,
                   uint32_t* __restrict__ qh2, uint32_t* __restrict__ ql2,
                   uint32_t* __restrict__ kh2, uint32_t* __restrict__ kl2) {
    int tok = blockIdx.x;
    int b = tok >> 11, s = tok & 2047;
    const float2* qr = (const float2*)(q + (size_t)tok*Dn);
    const float2* kr = (const float2*)(k + (size_t)tok*Dn);
    for (int p = threadIdx.x; p < 512; p += 256) {
        int h = p >> 6, hdp = p & 63;
        size_t o = ((size_t)(b*Hn + h)*Sn + s)*64 + hdp;
        float2 v = qr[p];
        uint32_t hi, lo;
        cvt_pair(v.x, v.y, hi, lo);
        qh2[o] = hi; ql2[o] = lo;
        v = kr[p];
        cvt_pair(v.x, v.y, hi, lo);
        kh2[o] = hi; kl2[o] = lo;
    }
}

// ---------------- convert V transposed: [bh][hd][kv pairs] ----------------
__global__ __launch_bounds__(256)
void cvt_v_kernel(const float* __restrict__ v,
                  uint32_t* __restrict__ vh2T, uint32_t* __restrict__ vl2T) {
    __shared__ float vs[64][129];
    int kv0 = blockIdx.x * 64;
    int bh = blockIdx.y, b = bh >> 3, h = bh & 7;
    const float* vb = v + ((size_t)b*Sn + kv0)*Dn + h*HDn;
    for (int idx = threadIdx.x; idx < 64*32; idx += 256) {
        int r = idx >> 5, c4 = (idx & 31) << 2;
        float4 t = *(const float4*)(vb + (size_t)r*Dn + c4);
        vs[r][c4] = t.x; vs[r][c4+1] = t.y; vs[r][c4+2] = t.z; vs[r][c4+3] = t.w;
    }
    __syncthreads();
    int hd  = threadIdx.x >> 1;
    int kp0 = (threadIdx.x & 1) * 16;
    uint32_t* oh = vh2T + ((size_t)bh*HDn + hd)*(Sn/2) + (kv0 >> 1) + kp0;
    uint32_t* ol = vl2T + ((size_t)bh*HDn + hd)*(Sn/2) + (kv0 >> 1) + kp0;
    for (int kp = 0; kp < 16; kp++) {
        float f0 = vs[2*(kp0+kp)  ][hd];
        float f1 = vs[2*(kp0+kp)+1][hd];
        uint32_t hi, lo;
        cvt_pair(f0, f1, hi, lo);
        oh[kp] = hi; ol[kp] = lo;
    }
}

// ---------------- fused flash attention ----------------
#define FQP 68   // qk/p smem pitch (u32)
#define FVP 36   // v smem pitch (u32)
#define FSM_U32 (4*64*FQP + 2*128*FVP)
#define FLASH_SMEM ((FSM_U32 + 512) * 4)

__global__ __launch_bounds__(256)
void flash_kernel(const uint32_t* __restrict__ qh2, const uint32_t* __restrict__ ql2,
                  const uint32_t* __restrict__ kh2, const uint32_t* __restrict__ kl2,
                  const uint32_t* __restrict__ vh2T, const uint32_t* __restrict__ vl2T,
                  const float* __restrict__ biasn, float* __restrict__ out) {
    extern __shared__ uint32_t smu[];
    uint32_t* qh  = smu;
    uint32_t* ql  = smu + 64*FQP;
    uint32_t* khb = smu + 2*64*FQP;   // K hi, reused as P hi
    uint32_t* klb = smu + 3*64*FQP;   // K lo, reused as P lo
    uint32_t* vhb = smu + 4*64*FQP;
    uint32_t* vlb = vhb + 128*FVP;
    float* m_s    = (float*)(vlb + 128*FVP);
    float* l_s    = m_s + 64;
    float* rmax   = l_s + 64;     // [2][64]
    float* rsum   = rmax + 128;   // [2][64]
    float* bias_s = rsum + 128;   // [128]

    int ti = gridDim.x - 1 - (int)blockIdx.x;   // heavy tiles first
    int bh = blockIdx.y, b = bh >> 3, h = bh & 7;
    int tid = threadIdx.x;
    int warp = tid >> 5, lane = tid & 31;
    int g = lane >> 2, t = lane & 3;
    int warpM  = (warp & 3) << 4;
    int grp    = warp >> 2;
    int warpNS = grp << 5;   // S col block (0/32)
    int warpNV = grp << 6;   // O col block (0/64)

    // stage Q once + init stats
    {
        size_t qoff = ((size_t)bh*Sn + (size_t)ti*64)*64;
        for (int idx = tid; idx < 1024; idx += 256) {
            int r = idx >> 4, c4 = (idx & 15) << 2;
            *(uint4*)&qh[r*FQP + c4] = *(const uint4*)(qh2 + qoff + (size_t)r*64 + c4);
            *(uint4*)&ql[r*FQP + c4] = *(const uint4*)(ql2 + qoff + (size_t)r*64 + c4);
        }
        if (tid < 64) { m_s[tid] = -INFINITY; l_s[tid] = 0.f; }
    }

    float acc[8][4] = {};
    int iloc0 = warpM + g;

    for (int jt = 0; jt <= ti; jt++) {
        __syncthreads();
        // stage K, V, bias slice
        size_t koff = ((size_t)bh*Sn + (size_t)jt*64)*64;
        for (int idx = tid; idx < 1024; idx += 256) {
            int r = idx >> 4, c4 = (idx & 15) << 2;
            *(uint4*)&khb[r*FQP + c4] = *(const uint4*)(kh2 + koff + (size_t)r*64 + c4);
            *(uint4*)&klb[r*FQP + c4] = *(const uint4*)(kl2 + koff + (size_t)r*64 + c4);
        }
        size_t voff = (size_t)bh*HDn*(Sn/2) + (size_t)jt*32;
        for (int idx = tid; idx < 1024; idx += 256) {
            int r = idx >> 3, c4 = (idx & 7) << 2;
            *(uint4*)&vhb[r*FVP + c4] = *(const uint4*)(vh2T + voff + (size_t)r*(Sn/2) + c4);
            *(uint4*)&vlb[r*FVP + c4] = *(const uint4*)(vl2T + voff + (size_t)r*(Sn/2) + c4);
        }
        if (tid < 128) {
            int n = (ti - jt)*64 - 63 + tid;
            bias_s[tid] = biasn[h*Sn + (n > 0 ? n : 0)];
        }
        __syncthreads();

        // ---- S = Q K^T (3x bf16 compensated) ----
        float sacc[4][4] = {};
        #pragma unroll
        for (int ks = 0; ks < 8; ks++) {
            int c0 = 8*ks + t, c1 = c0 + 4;
            int rA = iloc0*FQP;
            uint32_t ah0 = qh[rA + c0],           ah1 = qh[rA + 8*FQP + c0];
            uint32_t ah2 = qh[rA + c1],           ah3 = qh[rA + 8*FQP + c1];
            uint32_t al0 = ql[rA + c0],           al1 = ql[rA + 8*FQP + c0];
            uint32_t al2 = ql[rA + c1],           al3 = ql[rA + 8*FQP + c1];
            #pragma unroll
            for (int nt = 0; nt < 4; nt++) {
                int rB = (warpNS + nt*8 + g)*FQP;
                uint32_t kb0 = khb[rB + c0], kb1 = khb[rB + c1];
                uint32_t kc0 = klb[rB + c0], kc1 = klb[rB + c1];
                MMA_BF16(sacc[nt], ah0, ah1, ah2, ah3, kb0, kb1);
                MMA_BF16(sacc[nt], ah0, ah1, ah2, ah3, kc0, kc1);
                MMA_BF16(sacc[nt], al0, al1, al2, al3, kb0, kb1);
            }
        }

        // ---- bias + causal mask ----
        int i0 = ti*64 + iloc0;
        #pragma unroll
        for (int nt = 0; nt < 4; nt++) {
            int jloc = warpNS + nt*8 + 2*t;
            int j0 = jt*64 + jloc;
            int d00 = iloc0 - jloc + 63;
            sacc[nt][0] = (j0     <= i0    ) ? (sacc[nt][0] + bias_s[d00    ]) * SCALE_ : -INFINITY;
            sacc[nt][1] = (j0 + 1 <= i0    ) ? (sacc[nt][1] + bias_s[d00 - 1]) * SCALE_ : -INFINITY;
            sacc[nt][2] = (j0     <= i0 + 8) ? (sacc[nt][2] + bias_s[d00 + 8]) * SCALE_ : -INFINITY;
            sacc[nt][3] = (j0 + 1 <= i0 + 8) ? (sacc[nt][3] + bias_s[d00 + 7]) * SCALE_ : -INFINITY;
        }

        // ---- row max (quad shfl + cross-warp via smem) ----
        float mx0 = fmaxf(fmaxf(sacc[0][0], sacc[0][1]), fmaxf(sacc[1][0], sacc[1][1]));
        mx0 = fmaxf(mx0, fmaxf(fmaxf(sacc[2][0], sacc[2][1]), fmaxf(sacc[3][0], sacc[3][1])));
        float mx1 = fmaxf(fmaxf(sacc[0][2], sacc[0][3]), fmaxf(sacc[1][2], sacc[1][3]));
        mx1 = fmaxf(mx1, fmaxf(fmaxf(sacc[2][2], sacc[2][3]), fmaxf(sacc[3][2], sacc[3][3])));
        mx0 = fmaxf(mx0, __shfl_xor_sync(0xffffffffu, mx0, 1));
        mx0 = fmaxf(mx0, __shfl_xor_sync(0xffffffffu, mx0, 2));
        mx1 = fmaxf(mx1, __shfl_xor_sync(0xffffffffu, mx1, 1));
        mx1 = fmaxf(mx1, __shfl_xor_sync(0xffffffffu, mx1, 2));
        if (t == 0) {
            rmax[grp*64 + iloc0]     = mx0;
            rmax[grp*64 + iloc0 + 8] = mx1;
        }
        __syncthreads();

        float mold0 = m_s[iloc0], mold1 = m_s[iloc0 + 8];
        float mnew0 = fmaxf(mold0, fmaxf(rmax[iloc0],     rmax[64 + iloc0]));
        float mnew1 = fmaxf(mold1, fmaxf(rmax[iloc0 + 8], rmax[64 + iloc0 + 8]));
        float fac0 = __expf(mold0 - mnew0);
        float fac1 = __expf(mold1 - mnew1);

        // ---- exp, P write (into K buffers), row sums ----
        float sum0 = 0.f, sum1 = 0.f;
        #pragma unroll
        for (int nt = 0; nt < 4; nt++) {
            float p00 = __expf(sacc[nt][0] - mnew0);
            float p01 = __expf(sacc[nt][1] - mnew0);
            float p10 = __expf(sacc[nt][2] - mnew1);
            float p11 = __expf(sacc[nt][3] - mnew1);
            sum0 += p00 + p01; sum1 += p10 + p11;
            int cc = (warpNS >> 1) + nt*4 + t;
            uint32_t hi, lo;
            cvt_pair(p00, p01, hi, lo);
            khb[iloc0*FQP + cc] = hi; klb[iloc0*FQP + cc] = lo;
            cvt_pair(p10, p11, hi, lo);
            khb[(iloc0+8)*FQP + cc] = hi; klb[(iloc0+8)*FQP + cc] = lo;
        }
        sum0 += __shfl_xor_sync(0xffffffffu, sum0, 1);
        sum0 += __shfl_xor_sync(0xffffffffu, sum0, 2);
        sum1 += __shfl_xor_sync(0xffffffffu, sum1, 1);
        sum1 += __shfl_xor_sync(0xffffffffu, sum1, 2);
        if (t == 0) {
            rsum[grp*64 + iloc0]     = sum0;
            rsum[grp*64 + iloc0 + 8] = sum1;
        }

        // ---- rescale O ----
        #pragma unroll
        for (int nt = 0; nt < 8; nt++) {
            acc[nt][0] *= fac0; acc[nt][1] *= fac0;
            acc[nt][2] *= fac1; acc[nt][3] *= fac1;
        }
        __syncthreads();

        if (tid < 64) {
            float mo = m_s[tid];
            float mn = fmaxf(mo, fmaxf(rmax[tid], rmax[64 + tid]));
            l_s[tid] = l_s[tid] * __expf(mo - mn) + rsum[tid] + rsum[64 + tid];
            m_s[tid] = mn;
        }

        // ---- O += P V (3x bf16 compensated) ----
        #pragma unroll
        for (int ks = 0; ks < 4; ks++) {
            int c0 = 8*ks + t, c1 = c0 + 4;
            int rA = iloc0*FQP;
            uint32_t ah0 = khb[rA + c0],           ah1 = khb[rA + 8*FQP + c0];
            uint32_t ah2 = khb[rA + c1],           ah3 = khb[rA + 8*FQP + c1];
            uint32_t al0 = klb[rA + c0],           al1 = klb[rA + 8*FQP + c0];
            uint32_t al2 = klb[rA + c1],           al3 = klb[rA + 8*FQP + c1];
            #pragma unroll
            for (int nt = 0; nt < 8; nt++) {
                int rB = (warpNV + nt*8 + g)*FVP;
                uint32_t vb0 = vhb[rB + c0], vb1 = vhb[rB + c1];
                uint32_t vc0 = vlb[rB + c0], vc1 = vlb[rB + c1];
                MMA_BF16(acc[nt], ah0, ah1, ah2, ah3, vb0, vb1);
                MMA_BF16(acc[nt], ah0, ah1, ah2, ah3, vc0, vc1);
                MMA_BF16(acc[nt], al0, al1, al2, al3, vb0, vb1);
            }
        }
    }

    __syncthreads();
    float inv0 = 1.f / l_s[iloc0];
    float inv1 = 1.f / l_s[iloc0 + 8];
    int i0 = ti*64 + iloc0;
    #pragma unroll
    for (int nt = 0; nt < 8; nt++) {
        int col = warpNV + nt*8 + 2*t;
        float* op0 = out + ((size_t)b*Sn + i0)*Dn + h*HDn + col;
        float* op1 = op0 + 8*(size_t)Dn;
        *(float2*)op0 = make_float2(acc[nt][0]*inv0, acc[nt][1]*inv0);
        *(float2*)op1 = make_float2(acc[nt][2]*inv1, acc[nt][3]*inv1);
    }
}

// ---------------- orchestration ----------------
extern "C" void kernel_launch(void* const* d_in, const int* in_sizes, int n_in,
                              void* d_out, int out_size) {
    (void)in_sizes; (void)n_in; (void)out_size;
    const int*   x     = (const int*)  d_in[0];
    const float* tok   = (const float*)d_in[1];
    const float* rel   = (const float*)d_in[2];
    const float* ln_g  = (const float*)d_in[3];
    const float* ln_b  = (const float*)d_in[4];
    const float* Wqkv  = (const float*)d_in[5];
    const float* bqkv  = (const float*)d_in[6];
    const float* Wo    = (const float*)d_in[7];
    const float* bo    = (const float*)d_in[8];
    const float* W1    = (const float*)d_in[9];
    const float* b1    = (const float*)d_in[10];
    const float* W2    = (const float*)d_in[11];
    const float* b2    = (const float*)d_in[12];
    const float* lnf_g = (const float*)d_in[13];
    const float* lnf_b = (const float*)d_in[14];
    const float* Whead = (const float*)d_in[15];
    const float* bhead = (const float*)d_in[16];
    float* out = (float*)d_out;

    float *h, *ln, *qkv, *ao, *mid, *biasn;
    uint32_t *qh2, *ql2, *kh2, *kl2, *vh2T, *vl2T;
    cudaGetSymbolAddress((void**)&h,    g_h);
    cudaGetSymbolAddress((void**)&ln,   g_ln);
    cudaGetSymbolAddress((void**)&qkv,  g_qkv);
    cudaGetSymbolAddress((void**)&ao,   g_ao);
    cudaGetSymbolAddress((void**)&mid,  g_mid);
    cudaGetSymbolAddress((void**)&biasn,g_biasn);
    cudaGetSymbolAddress((void**)&qh2,  g_qh2);
    cudaGetSymbolAddress((void**)&ql2,  g_ql2);
    cudaGetSymbolAddress((void**)&kh2,  g_kh2);
    cudaGetSymbolAddress((void**)&kl2,  g_kl2);
    cudaGetSymbolAddress((void**)&vh2T, g_vh2T);
    cudaGetSymbolAddress((void**)&vl2T, g_vl2T);

    cudaFuncSetAttribute(flash_kernel, cudaFuncAttributeMaxDynamicSharedMemorySize,
                         FLASH_SMEM);

    const float* q = qkv;
    const float* k = qkv + (size_t)Mtok*Dn;
    const float* v = qkv + (size_t)2*Mtok*Dn;

    embed_kernel<<<Mtok, 256>>>(x, tok, h);
    bias_init_kernel<<<Sn/256, 256>>>(rel, biasn);

    dim3 gDD(Dn/TBN,  Mtok/TBM);
    dim3 gQKV(Dn/TBN, Mtok/TBM, 3);
    dim3 gDF(FFn/TBN, Mtok/TBM);
    dim3 gDV(Vn/TBN,  Mtok/TBM);

    for (int l = 0; l < Ln; l++) {
        ln_kernel<<<Mtok, 256>>>(h, ln_g + (size_t)(l*3+0)*Dn, ln_b + (size_t)(l*3+0)*Dn,
                                 nullptr, nullptr, ln, 0);
        tgemm_kernel<<<gQKV, 256>>>(ln, Wqkv + (size_t)l*3*Dn*Dn,
                                    bqkv + (size_t)l*3*Dn, nullptr, qkv,
                                    Mtok, Dn, Dn, 0,
                                    (size_t)Dn*Dn, (size_t)Dn, (size_t)Mtok*Dn);
        cvt_qk_kernel<<<Mtok, 256>>>(q, k, qh2, ql2, kh2, kl2);
        cvt_v_kernel<<<dim3(Sn/64, Bn*Hn), 256>>>(v, vh2T, vl2T);
        flash_kernel<<<dim3(Sn/64, Bn*Hn), 256, FLASH_SMEM>>>(
            qh2, ql2, kh2, kl2, vh2T, vl2T, biasn, ao);
        tgemm_kernel<<<gDD, 256>>>(ao, Wo + (size_t)l*Dn*Dn, bo + (size_t)l*Dn,
                                   h, h, Mtok, Dn, Dn, 0, 0, 0, 0);
        ln_kernel<<<Mtok, 256>>>(h, ln_g + (size_t)(l*3+1)*Dn, ln_b + (size_t)(l*3+1)*Dn,
                                 ln_g + (size_t)(l*3+2)*Dn, ln_b + (size_t)(l*3+2)*Dn, ln, 1);
        tgemm_kernel<<<gDF, 256>>>(ln, W1 + (size_t)l*Dn*FFn, b1 + (size_t)l*FFn,
                                   nullptr, mid, Mtok, FFn, Dn, 1, 0, 0, 0);
        tgemm_kernel<<<gDD, 256>>>(mid, W2 + (size_t)l*FFn*Dn, b2 + (size_t)l*Dn,
                                   h, h, Mtok, Dn, FFn, 0, 0, 0, 0);
    }

    ln_kernel<<<Mtok, 256>>>(h, lnf_g, lnf_b, nullptr, nullptr, ln, 0);
    tgemm_kernel<<<gDV, 256>>>(ln, Whead, bhead, nullptr, out, Mtok, Vn, Dn, 0, 0, 0, 0);
}

// round 5
// speedup vs baseline: 3.2119x; 1.1793x over previous
#include <cuda_runtime.h>
#include <cuda_bf16.h>
#include <math.h>
#include <stdint.h>

// ---------------- problem constants ----------------
#define Bn   2
#define Sn   2048
#define Dn   1024
#define Hn   8
#define HDn  128
#define Vn   32000
#define Ln   6
#define Mtok (Bn*Sn)      // 4096
#define FFn  (4*Dn)       // 4096
#define SCALE_ 0.08838834764831845f   // 128^-0.5

// ---------------- scratch (device globals; no cudaMalloc allowed) ----------------
__device__ float g_h  [(size_t)Mtok*Dn];
__device__ float g_ln [(size_t)Mtok*Dn];
__device__ float g_qkv[(size_t)3*Mtok*Dn];
__device__ float g_ao [(size_t)Mtok*Dn];
__device__ float g_mid[(size_t)Mtok*FFn];
// converted attention operands (bf16 hi/lo packed as u32 pairs)
__device__ uint32_t g_qh2[(size_t)Bn*Hn*Sn*64];
__device__ uint32_t g_ql2[(size_t)Bn*Hn*Sn*64];
__device__ uint32_t g_kh2[(size_t)Bn*Hn*Sn*64];
__device__ uint32_t g_kl2[(size_t)Bn*Hn*Sn*64];
__device__ uint32_t g_vh2T[(size_t)Bn*Hn*HDn*(Sn/2)];
__device__ uint32_t g_vl2T[(size_t)Bn*Hn*HDn*(Sn/2)];
__device__ float g_biasn[Hn*Sn];
// tf32-pre-rounded weights
#define OFF_WQKV ((size_t)0)
#define OFF_WO   (OFF_WQKV + (size_t)Ln*3*Dn*Dn)
#define OFF_W1   (OFF_WO   + (size_t)Ln*Dn*Dn)
#define OFF_W2   (OFF_W1   + (size_t)Ln*Dn*FFn)
#define OFF_WHEAD (OFF_W2  + (size_t)Ln*FFn*Dn)
#define NW_TOTAL (OFF_WHEAD + (size_t)Dn*Vn)
__device__ float g_w[NW_TOTAL];

// ---------------- helpers ----------------
__device__ __forceinline__ uint32_t f2tf32(float f) {
    uint32_t u;
    asm("cvt.rna.tf32.f32 %0, %1;" : "=r"(u) : "f"(f));
    return u;
}
__device__ __forceinline__ float tfv(float f) { return __uint_as_float(f2tf32(f)); }

__device__ __forceinline__ void cp16(void* dst_smem, const void* src) {
    uint32_t d = (uint32_t)__cvta_generic_to_shared(dst_smem);
    asm volatile("cp.async.cg.shared.global [%0], [%1], 16;" :: "r"(d), "l"(src));
}
#define CP_COMMIT asm volatile("cp.async.commit_group;" ::: "memory")

// split f0,f1 into bf16 hi/lo pairs packed as b32 (low half = first element)
__device__ __forceinline__ void cvt_pair(float f0, float f1, uint32_t& hi, uint32_t& lo) {
    __nv_bfloat16 h0 = __float2bfloat16(f0);
    __nv_bfloat16 h1 = __float2bfloat16(f1);
    __nv_bfloat16 l0 = __float2bfloat16(f0 - __bfloat162float(h0));
    __nv_bfloat16 l1 = __float2bfloat16(f1 - __bfloat162float(h1));
    hi = ((uint32_t)__bfloat16_as_ushort(h1) << 16) | (uint32_t)__bfloat16_as_ushort(h0);
    lo = ((uint32_t)__bfloat16_as_ushort(l1) << 16) | (uint32_t)__bfloat16_as_ushort(l0);
}

#define MMA_BF16(C, A0,A1,A2,A3, B0,B1) \
    asm volatile("mma.sync.aligned.m16n8k16.row.col.f32.bf16.bf16.f32 " \
        "{%0,%1,%2,%3}, {%4,%5,%6,%7}, {%8,%9}, {%0,%1,%2,%3};" \
        : "+f"((C)[0]), "+f"((C)[1]), "+f"((C)[2]), "+f"((C)[3]) \
        : "r"(A0), "r"(A1), "r"(A2), "r"(A3), "r"(B0), "r"(B1))

__device__ __forceinline__ float blockReduceSum(float v, float* sm) {
    int lane = threadIdx.x & 31, wid = threadIdx.x >> 5;
    #pragma unroll
    for (int o = 16; o > 0; o >>= 1) v += __shfl_xor_sync(0xffffffffu, v, o);
    if (lane == 0) sm[wid] = v;
    __syncthreads();
    if (threadIdx.x < 32) {
        float t = (threadIdx.x < 8) ? sm[threadIdx.x] : 0.f;
        #pragma unroll
        for (int o = 4; o > 0; o >>= 1) t += __shfl_xor_sync(0xffffffffu, t, o);
        if (threadIdx.x == 0) sm[0] = t;
    }
    __syncthreads();
    float r = sm[0];
    __syncthreads();
    return r;
}

// ---------------- weight tf32 pre-round ----------------
__global__ __launch_bounds__(256)
void cvtw_kernel(const float4* __restrict__ src, float4* __restrict__ dst, int n4) {
    int i = blockIdx.x * 256 + threadIdx.x;
    if (i < n4) {
        float4 v = src[i];
        dst[i] = make_float4(tfv(v.x), tfv(v.y), tfv(v.z), tfv(v.w));
    }
}

// ---------------- embedding gather ----------------
__global__ void embed_kernel(const int* __restrict__ x,
                             const float* __restrict__ emb,
                             float* __restrict__ h) {
    int t = blockIdx.x;
    int tok = x[t];
    ((float4*)(h + (size_t)t*Dn))[threadIdx.x] =
        ((const float4*)(emb + (size_t)tok*Dn))[threadIdx.x];
}

// ---------------- LayerNorm (optionally two LNs fused); output tf32-rounded ----------------
__global__ __launch_bounds__(256)
void ln_kernel(const float* __restrict__ x,
               const float* __restrict__ g,  const float* __restrict__ b,
               const float* __restrict__ g2, const float* __restrict__ b2,
               float* __restrict__ y, int dbl) {
    __shared__ float sm[32];
    int row = blockIdx.x;
    float4 v = ((const float4*)(x + (size_t)row*Dn))[threadIdx.x];
    float s  = v.x + v.y + v.z + v.w;
    float ss = v.x*v.x + v.y*v.y + v.z*v.z + v.w*v.w;
    float sum   = blockReduceSum(s, sm);
    float sumsq = blockReduceSum(ss, sm);
    float mean = sum * (1.f/Dn);
    float var  = sumsq * (1.f/Dn) - mean*mean;
    float r = rsqrtf(var + 1e-5f);
    int c = threadIdx.x * 4;
    float4 gv = *(const float4*)(g + c);
    float4 bv = *(const float4*)(b + c);
    float4 o;
    o.x = (v.x - mean)*r*gv.x + bv.x;
    o.y = (v.y - mean)*r*gv.y + bv.y;
    o.z = (v.z - mean)*r*gv.z + bv.z;
    o.w = (v.w - mean)*r*gv.w + bv.w;
    if (dbl) {
        s  = o.x + o.y + o.z + o.w;
        ss = o.x*o.x + o.y*o.y + o.z*o.z + o.w*o.w;
        sum   = blockReduceSum(s, sm);
        sumsq = blockReduceSum(ss, sm);
        mean = sum * (1.f/Dn);
        var  = sumsq * (1.f/Dn) - mean*mean;
        r = rsqrtf(var + 1e-5f);
        float4 g2v = *(const float4*)(g2 + c);
        float4 b2v = *(const float4*)(b2 + c);
        o.x = (o.x - mean)*r*g2v.x + b2v.x;
        o.y = (o.y - mean)*r*g2v.y + b2v.y;
        o.z = (o.z - mean)*r*g2v.z + b2v.z;
        o.w = (o.w - mean)*r*g2v.w + b2v.w;
    }
    o.x = tfv(o.x); o.y = tfv(o.y); o.z = tfv(o.z); o.w = tfv(o.w);
    ((float4*)(y + (size_t)row*Dn))[threadIdx.x] = o;
}

// ---------------- TF32 tensor-core GEMM, cp.async 4-stage pipeline ----------------
// Inputs MUST be tf32-pre-rounded (mma truncation is then exact).
#define TBM 128
#define TBN 128
#define SA_PITCH 20
#define SB_PITCH 136
#define STG_A (128*SA_PITCH)     // 2560 floats
#define STG_B (16*SB_PITCH)      // 2176 floats
#define STG   (STG_A + STG_B)    // 4736 floats
#define TG_SMEM (4*STG*4)        // 75776 bytes

__global__ __launch_bounds__(256, 2)
void tgemm_kernel(const float* __restrict__ A, const float* __restrict__ B,
                  const float* __restrict__ bias, const float* __restrict__ add,
                  float* __restrict__ C, int M, int N, int K,
                  int relu, int round_out,
                  size_t zB, size_t zBias, size_t zC) {
    extern __shared__ float smf[];

    B += (size_t)blockIdx.z * zB;
    if (bias) bias += (size_t)blockIdx.z * zBias;
    C += (size_t)blockIdx.z * zC;

    int tid  = threadIdx.x;
    int brow = blockIdx.y * TBM;
    int bcol = blockIdx.x * TBN;

    int warp = tid >> 5, lane = tid & 31;
    int gid = lane >> 2, tig = lane & 3;
    int warpM = (warp >> 2) * 64;
    int warpN = (warp & 3) * 32;

    const float* Ag = A + (size_t)brow * K;
    const float* Bg = B + bcol;

    // cp.async chunk mapping: 512 16B-chunks per array, 2 per thread each
    int am0 = tid >> 1,          ak0 = (tid & 1) << 3;            // rows 0..127, k 0/8 (two 16B)
    int bk0 = tid >> 5,          bn0 = (tid & 31) << 2;           // k 0..7,  n 0..124
    int bk1 = bk0 + 8;

    int nslab = K >> 4;
    auto issue = [&](int s) {
        float* As_ = smf + (s & 3) * STG;
        float* Bs_ = As_ + STG_A;
        int k0 = s << 4;
        const float* ag = Ag + (size_t)am0*K + k0 + ak0;
        cp16(As_ + am0*SA_PITCH + ak0,     ag);
        cp16(As_ + am0*SA_PITCH + ak0 + 4, ag + 4);
        cp16(Bs_ + bk0*SB_PITCH + bn0, Bg + (size_t)(k0+bk0)*N + bn0);
        cp16(Bs_ + bk1*SB_PITCH + bn0, Bg + (size_t)(k0+bk1)*N + bn0);
    };

    issue(0); CP_COMMIT;
    issue(1); CP_COMMIT;
    issue(2); CP_COMMIT;

    float acc[4][4][4] = {};

    for (int i = 0; i < nslab; i++) {
        asm volatile("cp.async.wait_group 2;" ::: "memory");
        __syncthreads();
        const float* As_ = smf + (i & 3) * STG;
        const float* Bs_ = As_ + STG_A;
        #pragma unroll
        for (int ks = 0; ks < 2; ks++) {
            int kb = ks * 8;
            uint32_t af[4][4], bf[4][2];
            #pragma unroll
            for (int mt = 0; mt < 4; mt++) {
                int r = warpM + mt*16 + gid;
                af[mt][0] = __float_as_uint(As_[(size_t)r    *SA_PITCH + kb + tig    ]);
                af[mt][1] = __float_as_uint(As_[(size_t)(r+8)*SA_PITCH + kb + tig    ]);
                af[mt][2] = __float_as_uint(As_[(size_t)r    *SA_PITCH + kb + tig + 4]);
                af[mt][3] = __float_as_uint(As_[(size_t)(r+8)*SA_PITCH + kb + tig + 4]);
            }
            #pragma unroll
            for (int nt = 0; nt < 4; nt++) {
                int c = warpN + nt*8 + gid;
                bf[nt][0] = __float_as_uint(Bs_[(size_t)(kb+tig  )*SB_PITCH + c]);
                bf[nt][1] = __float_as_uint(Bs_[(size_t)(kb+tig+4)*SB_PITCH + c]);
            }
            #pragma unroll
            for (int mt = 0; mt < 4; mt++)
                #pragma unroll
                for (int nt = 0; nt < 4; nt++) {
                    asm volatile(
                        "mma.sync.aligned.m16n8k8.row.col.f32.tf32.tf32.f32 "
                        "{%0,%1,%2,%3}, {%4,%5,%6,%7}, {%8,%9}, {%0,%1,%2,%3};\n"
                        : "+f"(acc[mt][nt][0]), "+f"(acc[mt][nt][1]),
                          "+f"(acc[mt][nt][2]), "+f"(acc[mt][nt][3])
                        : "r"(af[mt][0]), "r"(af[mt][1]), "r"(af[mt][2]), "r"(af[mt][3]),
                          "r"(bf[nt][0]), "r"(bf[nt][1]));
                }
        }
        if (i + 3 < nslab) issue(i + 3);
        CP_COMMIT;
    }

    #pragma unroll
    for (int mt = 0; mt < 4; mt++) {
        int r0 = brow + warpM + mt*16 + gid;
        int r1 = r0 + 8;
        #pragma unroll
        for (int nt = 0; nt < 4; nt++) {
            int c = bcol + warpN + nt*8 + tig*2;
            float v00 = acc[mt][nt][0], v01 = acc[mt][nt][1];
            float v10 = acc[mt][nt][2], v11 = acc[mt][nt][3];
            if (bias) {
                float bb0 = bias[c], bb1 = bias[c+1];
                v00 += bb0; v01 += bb1; v10 += bb0; v11 += bb1;
            }
            if (relu) {
                v00 = fmaxf(v00, 0.f); v01 = fmaxf(v01, 0.f);
                v10 = fmaxf(v10, 0.f); v11 = fmaxf(v11, 0.f);
            }
            if (round_out) {
                v00 = tfv(v00); v01 = tfv(v01);
                v10 = tfv(v10); v11 = tfv(v11);
            }
            if (add) {
                const float* ad0 = add + (size_t)r0*N + c;
                const float* ad1 = add + (size_t)r1*N + c;
                v00 += ad0[0]; v01 += ad0[1];
                v10 += ad1[0]; v11 += ad1[1];
            }
            *(float2*)(C + (size_t)r0*N + c) = make_float2(v00, v01);
            *(float2*)(C + (size_t)r1*N + c) = make_float2(v10, v11);
        }
    }
}

// ---------------- rel-pos bias table (layer-invariant) ----------------
__global__ void bias_init_kernel(const float* __restrict__ rel,
                                 float* __restrict__ biasn) {
    int n = blockIdx.x * 256 + threadIdx.x;
    if (n >= Sn) return;
    float inv_log8 = 1.0f / logf(8.0f);
    int bucket;
    if (n < 16) bucket = n;
    else {
        int vb = 16 + (int)((logf((float)n * (1.0f/16.0f)) * inv_log8) * 16.0f);
        bucket = vb < 31 ? vb : 31;
    }
    for (int h = 0; h < Hn; h++)
        biasn[h*Sn + n] = rel[bucket*Hn + h] * SCALE_;
}

// ---------------- convert Q,K to packed bf16 hi/lo (pairs along hd) ----------------
__global__ __launch_bounds__(256)
void cvt_qk_kernel(const float* __restrict__ q, const float* __restrict__ k,
                   uint32_t* __restrict__ qh2, uint32_t* __restrict__ ql2,
                   uint32_t* __restrict__ kh2, uint32_t* __restrict__ kl2) {
    int tok = blockIdx.x;
    int b = tok >> 11, s = tok & 2047;
    const float2* qr = (const float2*)(q + (size_t)tok*Dn);
    const float2* kr = (const float2*)(k + (size_t)tok*Dn);
    for (int p = threadIdx.x; p < 512; p += 256) {
        int h = p >> 6, hdp = p & 63;
        size_t o = ((size_t)(b*Hn + h)*Sn + s)*64 + hdp;
        float2 v = qr[p];
        uint32_t hi, lo;
        cvt_pair(v.x, v.y, hi, lo);
        qh2[o] = hi; ql2[o] = lo;
        v = kr[p];
        cvt_pair(v.x, v.y, hi, lo);
        kh2[o] = hi; kl2[o] = lo;
    }
}

// ---------------- convert V transposed: [bh][hd][kv pairs] ----------------
__global__ __launch_bounds__(256)
void cvt_v_kernel(const float* __restrict__ v,
                  uint32_t* __restrict__ vh2T, uint32_t* __restrict__ vl2T) {
    __shared__ float vs[64][129];
    int kv0 = blockIdx.x * 64;
    int bh = blockIdx.y, b = bh >> 3, h = bh & 7;
    const float* vb = v + ((size_t)b*Sn + kv0)*Dn + h*HDn;
    for (int idx = threadIdx.x; idx < 64*32; idx += 256) {
        int r = idx >> 5, c4 = (idx & 31) << 2;
        float4 t = *(const float4*)(vb + (size_t)r*Dn + c4);
        vs[r][c4] = t.x; vs[r][c4+1] = t.y; vs[r][c4+2] = t.z; vs[r][c4+3] = t.w;
    }
    __syncthreads();
    int hd  = threadIdx.x >> 1;
    int kp0 = (threadIdx.x & 1) * 16;
    uint32_t* oh = vh2T + ((size_t)bh*HDn + hd)*(Sn/2) + (kv0 >> 1) + kp0;
    uint32_t* ol = vl2T + ((size_t)bh*HDn + hd)*(Sn/2) + (kv0 >> 1) + kp0;
    for (int kp = 0; kp < 16; kp++) {
        float f0 = vs[2*(kp0+kp)  ][hd];
        float f1 = vs[2*(kp0+kp)+1][hd];
        uint32_t hi, lo;
        cvt_pair(f0, f1, hi, lo);
        oh[kp] = hi; ol[kp] = lo;
    }
}

// ---------------- fused flash attention ----------------
#define FQP 68   // qk/p smem pitch (u32)
#define FVP 36   // v smem pitch (u32)
#define FSM_U32 (4*64*FQP + 2*128*FVP)
#define FLASH_SMEM ((FSM_U32 + 512) * 4)

__global__ __launch_bounds__(256)
void flash_kernel(const uint32_t* __restrict__ qh2, const uint32_t* __restrict__ ql2,
                  const uint32_t* __restrict__ kh2, const uint32_t* __restrict__ kl2,
                  const uint32_t* __restrict__ vh2T, const uint32_t* __restrict__ vl2T,
                  const float* __restrict__ biasn, float* __restrict__ out) {
    extern __shared__ uint32_t smu[];
    uint32_t* qh  = smu;
    uint32_t* ql  = smu + 64*FQP;
    uint32_t* khb = smu + 2*64*FQP;   // K hi, reused as P hi
    uint32_t* klb = smu + 3*64*FQP;   // K lo, reused as P lo
    uint32_t* vhb = smu + 4*64*FQP;
    uint32_t* vlb = vhb + 128*FVP;
    float* m_s    = (float*)(vlb + 128*FVP);
    float* l_s    = m_s + 64;
    float* rmax   = l_s + 64;     // [2][64]
    float* rsum   = rmax + 128;   // [2][64]
    float* bias_s = rsum + 128;   // [128]

    int ti = gridDim.x - 1 - (int)blockIdx.x;   // heavy tiles first
    int bh = blockIdx.y, b = bh >> 3, h = bh & 7;
    int tid = threadIdx.x;
    int warp = tid >> 5, lane = tid & 31;
    int g = lane >> 2, t = lane & 3;
    int warpM  = (warp & 3) << 4;
    int grp    = warp >> 2;
    int warpNS = grp << 5;   // S col block (0/32)
    int warpNV = grp << 6;   // O col block (0/64)

    // stage Q once + init stats
    {
        size_t qoff = ((size_t)bh*Sn + (size_t)ti*64)*64;
        for (int idx = tid; idx < 1024; idx += 256) {
            int r = idx >> 4, c4 = (idx & 15) << 2;
            *(uint4*)&qh[r*FQP + c4] = *(const uint4*)(qh2 + qoff + (size_t)r*64 + c4);
            *(uint4*)&ql[r*FQP + c4] = *(const uint4*)(ql2 + qoff + (size_t)r*64 + c4);
        }
        if (tid < 64) { m_s[tid] = -INFINITY; l_s[tid] = 0.f; }
    }

    float acc[8][4] = {};
    int iloc0 = warpM + g;

    for (int jt = 0; jt <= ti; jt++) {
        __syncthreads();
        // stage K, V, bias slice
        size_t koff = ((size_t)bh*Sn + (size_t)jt*64)*64;
        for (int idx = tid; idx < 1024; idx += 256) {
            int r = idx >> 4, c4 = (idx & 15) << 2;
            *(uint4*)&khb[r*FQP + c4] = *(const uint4*)(kh2 + koff + (size_t)r*64 + c4);
            *(uint4*)&klb[r*FQP + c4] = *(const uint4*)(kl2 + koff + (size_t)r*64 + c4);
        }
        size_t voff = (size_t)bh*HDn*(Sn/2) + (size_t)jt*32;
        for (int idx = tid; idx < 1024; idx += 256) {
            int r = idx >> 3, c4 = (idx & 7) << 2;
            *(uint4*)&vhb[r*FVP + c4] = *(const uint4*)(vh2T + voff + (size_t)r*(Sn/2) + c4);
            *(uint4*)&vlb[r*FVP + c4] = *(const uint4*)(vl2T + voff + (size_t)r*(Sn/2) + c4);
        }
        if (tid < 128) {
            int n = (ti - jt)*64 - 63 + tid;
            bias_s[tid] = biasn[h*Sn + (n > 0 ? n : 0)];
        }
        __syncthreads();

        // ---- S = Q K^T (3x bf16 compensated) ----
        float sacc[4][4] = {};
        #pragma unroll
        for (int ks = 0; ks < 8; ks++) {
            int c0 = 8*ks + t, c1 = c0 + 4;
            int rA = iloc0*FQP;
            uint32_t ah0 = qh[rA + c0],           ah1 = qh[rA + 8*FQP + c0];
            uint32_t ah2 = qh[rA + c1],           ah3 = qh[rA + 8*FQP + c1];
            uint32_t al0 = ql[rA + c0],           al1 = ql[rA + 8*FQP + c0];
            uint32_t al2 = ql[rA + c1],           al3 = ql[rA + 8*FQP + c1];
            #pragma unroll
            for (int nt = 0; nt < 4; nt++) {
                int rB = (warpNS + nt*8 + g)*FQP;
                uint32_t kb0 = khb[rB + c0], kb1 = khb[rB + c1];
                uint32_t kc0 = klb[rB + c0], kc1 = klb[rB + c1];
                MMA_BF16(sacc[nt], ah0, ah1, ah2, ah3, kb0, kb1);
                MMA_BF16(sacc[nt], ah0, ah1, ah2, ah3, kc0, kc1);
                MMA_BF16(sacc[nt], al0, al1, al2, al3, kb0, kb1);
            }
        }

        // ---- bias + causal mask ----
        int i0 = ti*64 + iloc0;
        #pragma unroll
        for (int nt = 0; nt < 4; nt++) {
            int jloc = warpNS + nt*8 + 2*t;
            int j0 = jt*64 + jloc;
            int d00 = iloc0 - jloc + 63;
            sacc[nt][0] = (j0     <= i0    ) ? (sacc[nt][0] + bias_s[d00    ]) * SCALE_ : -INFINITY;
            sacc[nt][1] = (j0 + 1 <= i0    ) ? (sacc[nt][1] + bias_s[d00 - 1]) * SCALE_ : -INFINITY;
            sacc[nt][2] = (j0     <= i0 + 8) ? (sacc[nt][2] + bias_s[d00 + 8]) * SCALE_ : -INFINITY;
            sacc[nt][3] = (j0 + 1 <= i0 + 8) ? (sacc[nt][3] + bias_s[d00 + 7]) * SCALE_ : -INFINITY;
        }

        // ---- row max (quad shfl + cross-warp via smem) ----
        float mx0 = fmaxf(fmaxf(sacc[0][0], sacc[0][1]), fmaxf(sacc[1][0], sacc[1][1]));
        mx0 = fmaxf(mx0, fmaxf(fmaxf(sacc[2][0], sacc[2][1]), fmaxf(sacc[3][0], sacc[3][1])));
        float mx1 = fmaxf(fmaxf(sacc[0][2], sacc[0][3]), fmaxf(sacc[1][2], sacc[1][3]));
        mx1 = fmaxf(mx1, fmaxf(fmaxf(sacc[2][2], sacc[2][3]), fmaxf(sacc[3][2], sacc[3][3])));
        mx0 = fmaxf(mx0, __shfl_xor_sync(0xffffffffu, mx0, 1));
        mx0 = fmaxf(mx0, __shfl_xor_sync(0xffffffffu, mx0, 2));
        mx1 = fmaxf(mx1, __shfl_xor_sync(0xffffffffu, mx1, 1));
        mx1 = fmaxf(mx1, __shfl_xor_sync(0xffffffffu, mx1, 2));
        if (t == 0) {
            rmax[grp*64 + iloc0]     = mx0;
            rmax[grp*64 + iloc0 + 8] = mx1;
        }
        __syncthreads();

        float mold0 = m_s[iloc0], mold1 = m_s[iloc0 + 8];
        float mnew0 = fmaxf(mold0, fmaxf(rmax[iloc0],     rmax[64 + iloc0]));
        float mnew1 = fmaxf(mold1, fmaxf(rmax[iloc0 + 8], rmax[64 + iloc0 + 8]));
        float fac0 = __expf(mold0 - mnew0);
        float fac1 = __expf(mold1 - mnew1);

        // ---- exp, P write (into K buffers), row sums ----
        float sum0 = 0.f, sum1 = 0.f;
        #pragma unroll
        for (int nt = 0; nt < 4; nt++) {
            float p00 = __expf(sacc[nt][0] - mnew0);
            float p01 = __expf(sacc[nt][1] - mnew0);
            float p10 = __expf(sacc[nt][2] - mnew1);
            float p11 = __expf(sacc[nt][3] - mnew1);
            sum0 += p00 + p01; sum1 += p10 + p11;
            int cc = (warpNS >> 1) + nt*4 + t;
            uint32_t hi, lo;
            cvt_pair(p00, p01, hi, lo);
            khb[iloc0*FQP + cc] = hi; klb[iloc0*FQP + cc] = lo;
            cvt_pair(p10, p11, hi, lo);
            khb[(iloc0+8)*FQP + cc] = hi; klb[(iloc0+8)*FQP + cc] = lo;
        }
        sum0 += __shfl_xor_sync(0xffffffffu, sum0, 1);
        sum0 += __shfl_xor_sync(0xffffffffu, sum0, 2);
        sum1 += __shfl_xor_sync(0xffffffffu, sum1, 1);
        sum1 += __shfl_xor_sync(0xffffffffu, sum1, 2);
        if (t == 0) {
            rsum[grp*64 + iloc0]     = sum0;
            rsum[grp*64 + iloc0 + 8] = sum1;
        }

        // ---- rescale O ----
        #pragma unroll
        for (int nt = 0; nt < 8; nt++) {
            acc[nt][0] *= fac0; acc[nt][1] *= fac0;
            acc[nt][2] *= fac1; acc[nt][3] *= fac1;
        }
        __syncthreads();

        if (tid < 64) {
            float mo = m_s[tid];
            float mn = fmaxf(mo, fmaxf(rmax[tid], rmax[64 + tid]));
            l_s[tid] = l_s[tid] * __expf(mo - mn) + rsum[tid] + rsum[64 + tid];
            m_s[tid] = mn;
        }

        // ---- O += P V (3x bf16 compensated) ----
        #pragma unroll
        for (int ks = 0; ks < 4; ks++) {
            int c0 = 8*ks + t, c1 = c0 + 4;
            int rA = iloc0*FQP;
            uint32_t ah0 = khb[rA + c0],           ah1 = khb[rA + 8*FQP + c0];
            uint32_t ah2 = khb[rA + c1],           ah3 = khb[rA + 8*FQP + c1];
            uint32_t al0 = klb[rA + c0],           al1 = klb[rA + 8*FQP + c0];
            uint32_t al2 = klb[rA + c1],           al3 = klb[rA + 8*FQP + c1];
            #pragma unroll
            for (int nt = 0; nt < 8; nt++) {
                int rB = (warpNV + nt*8 + g)*FVP;
                uint32_t vb0 = vhb[rB + c0], vb1 = vhb[rB + c1];
                uint32_t vc0 = vlb[rB + c0], vc1 = vlb[rB + c1];
                MMA_BF16(acc[nt], ah0, ah1, ah2, ah3, vb0, vb1);
                MMA_BF16(acc[nt], ah0, ah1, ah2, ah3, vc0, vc1);
                MMA_BF16(acc[nt], al0, al1, al2, al3, vb0, vb1);
            }
        }
    }

    __syncthreads();
    float inv0 = 1.f / l_s[iloc0];
    float inv1 = 1.f / l_s[iloc0 + 8];
    int i0 = ti*64 + iloc0;
    #pragma unroll
    for (int nt = 0; nt < 8; nt++) {
        int col = warpNV + nt*8 + 2*t;
        float* op0 = out + ((size_t)b*Sn + i0)*Dn + h*HDn + col;
        float* op1 = op0 + 8*(size_t)Dn;
        *(float2*)op0 = make_float2(tfv(acc[nt][0]*inv0), tfv(acc[nt][1]*inv0));
        *(float2*)op1 = make_float2(tfv(acc[nt][2]*inv1), tfv(acc[nt][3]*inv1));
    }
}

// ---------------- orchestration ----------------
extern "C" void kernel_launch(void* const* d_in, const int* in_sizes, int n_in,
                              void* d_out, int out_size) {
    (void)in_sizes; (void)n_in; (void)out_size;
    const int*   x     = (const int*)  d_in[0];
    const float* tok   = (const float*)d_in[1];
    const float* rel   = (const float*)d_in[2];
    const float* ln_g  = (const float*)d_in[3];
    const float* ln_b  = (const float*)d_in[4];
    const float* Wqkv  = (const float*)d_in[5];
    const float* bqkv  = (const float*)d_in[6];
    const float* Wo    = (const float*)d_in[7];
    const float* bo    = (const float*)d_in[8];
    const float* W1    = (const float*)d_in[9];
    const float* b1    = (const float*)d_in[10];
    const float* W2    = (const float*)d_in[11];
    const float* b2    = (const float*)d_in[12];
    const float* lnf_g = (const float*)d_in[13];
    const float* lnf_b = (const float*)d_in[14];
    const float* Whead = (const float*)d_in[15];
    const float* bhead = (const float*)d_in[16];
    float* out = (float*)d_out;

    float *h, *ln, *qkv, *ao, *mid, *biasn, *w;
    uint32_t *qh2, *ql2, *kh2, *kl2, *vh2T, *vl2T;
    cudaGetSymbolAddress((void**)&h,    g_h);
    cudaGetSymbolAddress((void**)&ln,   g_ln);
    cudaGetSymbolAddress((void**)&qkv,  g_qkv);
    cudaGetSymbolAddress((void**)&ao,   g_ao);
    cudaGetSymbolAddress((void**)&mid,  g_mid);
    cudaGetSymbolAddress((void**)&biasn,g_biasn);
    cudaGetSymbolAddress((void**)&w,    g_w);
    cudaGetSymbolAddress((void**)&qh2,  g_qh2);
    cudaGetSymbolAddress((void**)&ql2,  g_ql2);
    cudaGetSymbolAddress((void**)&kh2,  g_kh2);
    cudaGetSymbolAddress((void**)&kl2,  g_kl2);
    cudaGetSymbolAddress((void**)&vh2T, g_vh2T);
    cudaGetSymbolAddress((void**)&vl2T, g_vl2T);

    cudaFuncSetAttribute(flash_kernel, cudaFuncAttributeMaxDynamicSharedMemorySize,
                         FLASH_SMEM);
    cudaFuncSetAttribute(tgemm_kernel, cudaFuncAttributeMaxDynamicSharedMemorySize,
                         TG_SMEM);

    // pre-round all weights to tf32 (per replay; ~130us at HBM speed)
    {
        struct { const float* s; float* d; size_t n; } cv[5] = {
            { Wqkv,  w + OFF_WQKV,  (size_t)Ln*3*Dn*Dn },
            { Wo,    w + OFF_WO,    (size_t)Ln*Dn*Dn   },
            { W1,    w + OFF_W1,    (size_t)Ln*Dn*FFn  },
            { W2,    w + OFF_W2,    (size_t)Ln*FFn*Dn  },
            { Whead, w + OFF_WHEAD, (size_t)Dn*Vn      },
        };
        for (int i = 0; i < 5; i++) {
            int n4 = (int)(cv[i].n >> 2);
            cvtw_kernel<<<(n4 + 255)/256, 256>>>((const float4*)cv[i].s,
                                                 (float4*)cv[i].d, n4);
        }
    }

    const float* q = qkv;
    const float* k = qkv + (size_t)Mtok*Dn;
    const float* v = qkv + (size_t)2*Mtok*Dn;

    embed_kernel<<<Mtok, 256>>>(x, tok, h);
    bias_init_kernel<<<Sn/256, 256>>>(rel, biasn);

    dim3 gDD(Dn/TBN,  Mtok/TBM);
    dim3 gQKV(Dn/TBN, Mtok/TBM, 3);
    dim3 gDF(FFn/TBN, Mtok/TBM);
    dim3 gDV(Vn/TBN,  Mtok/TBM);

    for (int l = 0; l < Ln; l++) {
        ln_kernel<<<Mtok, 256>>>(h, ln_g + (size_t)(l*3+0)*Dn, ln_b + (size_t)(l*3+0)*Dn,
                                 nullptr, nullptr, ln, 0);
        tgemm_kernel<<<gQKV, 256, TG_SMEM>>>(ln, w + OFF_WQKV + (size_t)l*3*Dn*Dn,
                                    bqkv + (size_t)l*3*Dn, nullptr, qkv,
                                    Mtok, Dn, Dn, 0, 0,
                                    (size_t)Dn*Dn, (size_t)Dn, (size_t)Mtok*Dn);
        cvt_qk_kernel<<<Mtok, 256>>>(q, k, qh2, ql2, kh2, kl2);
        cvt_v_kernel<<<dim3(Sn/64, Bn*Hn), 256>>>(v, vh2T, vl2T);
        flash_kernel<<<dim3(Sn/64, Bn*Hn), 256, FLASH_SMEM>>>(
            qh2, ql2, kh2, kl2, vh2T, vl2T, biasn, ao);
        tgemm_kernel<<<gDD, 256, TG_SMEM>>>(ao, w + OFF_WO + (size_t)l*Dn*Dn,
                                   bo + (size_t)l*Dn, h, h,
                                   Mtok, Dn, Dn, 0, 0, 0, 0, 0);
        ln_kernel<<<Mtok, 256>>>(h, ln_g + (size_t)(l*3+1)*Dn, ln_b + (size_t)(l*3+1)*Dn,
                                 ln_g + (size_t)(l*3+2)*Dn, ln_b + (size_t)(l*3+2)*Dn, ln, 1);
        tgemm_kernel<<<gDF, 256, TG_SMEM>>>(ln, w + OFF_W1 + (size_t)l*Dn*FFn,
                                   b1 + (size_t)l*FFn, nullptr, mid,
                                   Mtok, FFn, Dn, 1, 1, 0, 0, 0);
        tgemm_kernel<<<gDD, 256, TG_SMEM>>>(mid, w + OFF_W2 + (size_t)l*FFn*Dn,
                                   b2 + (size_t)l*Dn, h, h,
                                   Mtok, Dn, FFn, 0, 0, 0, 0, 0);
    }

    ln_kernel<<<Mtok, 256>>>(h, lnf_g, lnf_b, nullptr, nullptr, ln, 0);
    tgemm_kernel<<<gDV, 256, TG_SMEM>>>(ln, w + OFF_WHEAD, bhead, nullptr, out,
                               Mtok, Vn, Dn, 0, 0, 0, 0, 0);
}